// round 1
// baseline (speedup 1.0000x reference)
#include <cuda_runtime.h>
#include <math.h>

// Problem constants
#define Bn 4
#define Sn 2048
#define DIMn 1024
#define Hn 16
#define Dn 64
#define Tn (Bn*Sn)      // 8192 tokens
#define HDn 1024
#define WIN 512

// Scratch (device globals; no allocation allowed in kernel_launch)
__device__ float g_q[(size_t)Tn*HDn];
__device__ float g_k[(size_t)Tn*HDn];
__device__ float g_v[(size_t)Tn*HDn];
__device__ float g_ao[(size_t)Tn*HDn];
__device__ float g_mix[Tn*Hn];
__device__ float g_gate[Tn*Hn];

// ---------------------------------------------------------------------------
// 128x128x8 SGEMM, 256 threads, 8x8 register tile, gmem prefetch.
// A: MxK row-major (K=1024). B: KxNB row-major. Output row stride fixed 1024.
// Columns >= 1024 are routed to C1 (used to split the KV projection).
// ---------------------------------------------------------------------------
__global__ void __launch_bounds__(256) sgemm128(
    const float* __restrict__ A, const float* __restrict__ Bm,
    float* __restrict__ C0, float* __restrict__ C1, int K, int NB)
{
    __shared__ float As[8][128];   // transposed A tile
    __shared__ float Bs[8][128];

    const int tid  = threadIdx.x;
    const int brow = blockIdx.y * 128;
    const int bcol = blockIdx.x * 128;

    const int a_row = tid >> 1;            // 0..127
    const int a_k   = (tid & 1) << 2;      // 0 or 4
    const int b_row = tid >> 5;            // 0..7
    const int b_col = (tid & 31) << 2;     // 0..124

    const int tm = (tid >> 4) << 3;        // 0..120
    const int tn = (tid & 15) << 3;        // 0..120

    float acc[8][8];
#pragma unroll
    for (int i = 0; i < 8; i++)
#pragma unroll
        for (int j = 0; j < 8; j++) acc[i][j] = 0.f;

    const float* Ap = A  + (size_t)(brow + a_row) * K + a_k;
    const float* Bp = Bm + (size_t)b_row * NB + bcol + b_col;

    float4 av = *(const float4*)(Ap);
    float4 bv = *(const float4*)(Bp);

    for (int k0 = 0; k0 < K; k0 += 8) {
        As[a_k + 0][a_row] = av.x;
        As[a_k + 1][a_row] = av.y;
        As[a_k + 2][a_row] = av.z;
        As[a_k + 3][a_row] = av.w;
        *(float4*)(&Bs[b_row][b_col]) = bv;
        __syncthreads();

        if (k0 + 8 < K) {  // prefetch next tile while computing
            av = *(const float4*)(Ap + k0 + 8);
            bv = *(const float4*)(Bp + (size_t)(k0 + 8) * NB);
        }

#pragma unroll
        for (int kk = 0; kk < 8; kk++) {
            float af[8], bf[8];
            *(float4*)(af)     = *(const float4*)(&As[kk][tm]);
            *(float4*)(af + 4) = *(const float4*)(&As[kk][tm + 4]);
            *(float4*)(bf)     = *(const float4*)(&Bs[kk][tn]);
            *(float4*)(bf + 4) = *(const float4*)(&Bs[kk][tn + 4]);
#pragma unroll
            for (int i = 0; i < 8; i++)
#pragma unroll
                for (int j = 0; j < 8; j++)
                    acc[i][j] += af[i] * bf[j];
        }
        __syncthreads();
    }

    const int colg = bcol + tn;
    float* Cb;
    int cc;
    if (colg < 1024) { Cb = C0; cc = colg; }
    else             { Cb = C1; cc = colg - 1024; }

#pragma unroll
    for (int i = 0; i < 8; i++) {
        float4 w0 = make_float4(acc[i][0], acc[i][1], acc[i][2], acc[i][3]);
        float4 w1 = make_float4(acc[i][4], acc[i][5], acc[i][6], acc[i][7]);
        float* cp = Cb + (size_t)(brow + tm + i) * 1024 + cc;
        *(float4*)(cp)     = w0;
        *(float4*)(cp + 4) = w1;
    }
}

// ---------------------------------------------------------------------------
// mix/gate: (8192 x 1024) @ [Wmix | Wgate] (1024 x 32), sigmoid epilogue.
// ---------------------------------------------------------------------------
__global__ void __launch_bounds__(256) mixgate(
    const float* __restrict__ tokens, const float* __restrict__ Wmix,
    const float* __restrict__ Wgate, float* __restrict__ gmix,
    float* __restrict__ ggate)
{
    __shared__ float Ts[128][65];
    __shared__ float Ws[64][32];

    const int tid  = threadIdx.x;
    const int row0 = blockIdx.x * 128;
    const int r  = tid >> 1;          // 0..127
    const int cg = (tid & 1) << 4;    // 0 or 16

    float acc[16];
#pragma unroll
    for (int c = 0; c < 16; c++) acc[c] = 0.f;

    for (int k0 = 0; k0 < 1024; k0 += 64) {
#pragma unroll
        for (int u = 0; u < 8; u++) {              // 2048 float4s of tokens
            int fi = tid + u * 256;
            int rr = fi >> 4;
            int cc = (fi & 15) << 2;
            float4 x = *(const float4*)(tokens + (size_t)(row0 + rr) * 1024 + k0 + cc);
            Ts[rr][cc]     = x.x;
            Ts[rr][cc + 1] = x.y;
            Ts[rr][cc + 2] = x.z;
            Ts[rr][cc + 3] = x.w;
        }
#pragma unroll
        for (int u = 0; u < 8; u++) {              // 2048 weight floats
            int fi = tid + u * 256;
            int rr = fi >> 5;
            int cc = fi & 31;
            Ws[rr][cc] = (cc < 16) ? Wmix[(k0 + rr) * 16 + cc]
                                   : Wgate[(k0 + rr) * 16 + (cc - 16)];
        }
        __syncthreads();

        for (int kk = 0; kk < 64; kk++) {
            float a = Ts[r][kk];
#pragma unroll
            for (int c = 0; c < 16; c++) acc[c] += a * Ws[kk][cg + c];
        }
        __syncthreads();
    }

    const int t = row0 + r;
#pragma unroll
    for (int c = 0; c < 16; c++) {
        float sg = 1.0f / (1.0f + expf(-acc[c]));
        int col = cg + c;
        if (col < 16) gmix[t * 16 + col] = sg;
        else          ggate[t * 16 + (col - 16)] = sg;
    }
}

// ---------------------------------------------------------------------------
// Interleaved RoPE on q (with 1/sqrt(D) scale) and k.
// ---------------------------------------------------------------------------
__global__ void rope_qk(float* __restrict__ q, float* __restrict__ k)
{
    int idx = blockIdx.x * blockDim.x + threadIdx.x;   // over Tn*Hn*32 pairs
    if (idx >= Tn * Hn * 32) return;
    int i = idx & 31;
    int h = (idx >> 5) & 15;
    int t = idx >> 9;
    int s = t & (Sn - 1);

    float inv = powf(10000.0f, -(float)(2 * i) * (1.0f / 64.0f));
    float ang = (float)s * inv;
    float sn, cs;
    sincosf(ang, &sn, &cs);

    size_t base = (size_t)t * HDn + h * Dn + 2 * i;
    const float scale = 0.125f;   // D^-0.5
    float x0 = q[base], x1 = q[base + 1];
    q[base]     = (x0 * cs - x1 * sn) * scale;
    q[base + 1] = (x1 * cs + x0 * sn) * scale;
    x0 = k[base]; x1 = k[base + 1];
    k[base]     = x0 * cs - x1 * sn;
    k[base + 1] = x1 * cs + x0 * sn;
}

// ---------------------------------------------------------------------------
// v = v + (value_residual - v) * mix
// v token-major (b,s,h,d); value_residual (b,h,s,d).
// ---------------------------------------------------------------------------
__global__ void vmix(float* __restrict__ v, const float* __restrict__ vr,
                     const float* __restrict__ mix)
{
    int idx = blockIdx.x * blockDim.x + threadIdx.x;
    if (idx >= Tn * HDn) return;
    int d = idx & 63;
    int h = (idx >> 6) & 15;
    int t = idx >> 10;
    int s = t & (Sn - 1);
    int b = t >> 11;
    float m  = mix[t * Hn + h];
    float vv = v[idx];
    float rr = vr[(((size_t)b * Hn + h) * Sn + s) * Dn + d];
    v[idx] = vv + (rr - vv) * m;
}

// ---------------------------------------------------------------------------
// Sliding-window flash attention. Block = (query-tile 64, head, batch).
// 256 threads as 16x16, 4x4 microtiles. Online softmax. Gate in epilogue.
// ---------------------------------------------------------------------------
#define PADW 65
__global__ void __launch_bounds__(256) attn_win(
    const float* __restrict__ q, const float* __restrict__ k,
    const float* __restrict__ v, const float* __restrict__ gate,
    float* __restrict__ out)
{
    extern __shared__ float sm[];
    float* Qs = sm;
    float* Ks = sm + 64 * PADW;
    float* Vs = sm + 2 * 64 * PADW;
    float* Ps = sm + 3 * 64 * PADW;

    const int b  = blockIdx.z;
    const int h  = blockIdx.y;
    const int q0 = blockIdx.x * 64;
    const int tid = threadIdx.x;
    const int ty = tid >> 4, tx = tid & 15;
    const int r0 = ty << 2, c0 = tx << 2;

    const float* qb = q + (size_t)b * Sn * HDn + h * Dn;
    const float* kb = k + (size_t)b * Sn * HDn + h * Dn;
    const float* vb = v + (size_t)b * Sn * HDn + h * Dn;

    // load Q tile (64 rows x 64 dims)
    {
        int r  = tid >> 2;
        int cc = (tid & 3) << 4;
        const float* src = qb + (size_t)(q0 + r) * HDn + cc;
        float* dst = Qs + r * PADW + cc;
#pragma unroll
        for (int u = 0; u < 4; u++) {
            float4 x = *(const float4*)(src + 4 * u);
            dst[4 * u]     = x.x;
            dst[4 * u + 1] = x.y;
            dst[4 * u + 2] = x.z;
            dst[4 * u + 3] = x.w;
        }
    }

    float m_i[4], l_i[4], o[4][4];
#pragma unroll
    for (int i = 0; i < 4; i++) {
        m_i[i] = -1e30f;
        l_i[i] = 0.f;
#pragma unroll
        for (int j = 0; j < 4; j++) o[i][j] = 0.f;
    }

    int jt_lo = (q0 >= WIN) ? ((q0 - WIN) >> 6) : 0;
    int jt_hi = q0 >> 6;

    for (int jt = jt_lo; jt <= jt_hi; jt++) {
        int j0 = jt << 6;
        // load K, V tiles
        {
            int r  = tid >> 2;
            int cc = (tid & 3) << 4;
            const float* ksrc = kb + (size_t)(j0 + r) * HDn + cc;
            const float* vsrc = vb + (size_t)(j0 + r) * HDn + cc;
            float* kd = Ks + r * PADW + cc;
            float* vd = Vs + r * PADW + cc;
#pragma unroll
            for (int u = 0; u < 4; u++) {
                float4 x = *(const float4*)(ksrc + 4 * u);
                kd[4 * u] = x.x; kd[4 * u + 1] = x.y; kd[4 * u + 2] = x.z; kd[4 * u + 3] = x.w;
                float4 y = *(const float4*)(vsrc + 4 * u);
                vd[4 * u] = y.x; vd[4 * u + 1] = y.y; vd[4 * u + 2] = y.z; vd[4 * u + 3] = y.w;
            }
        }
        __syncthreads();

        // S = Q @ K^T  (4x4 per thread)
        float s[4][4];
#pragma unroll
        for (int i = 0; i < 4; i++)
#pragma unroll
            for (int j = 0; j < 4; j++) s[i][j] = 0.f;

        for (int kd = 0; kd < 64; kd++) {
            float a0 = Qs[(r0 + 0) * PADW + kd];
            float a1 = Qs[(r0 + 1) * PADW + kd];
            float a2 = Qs[(r0 + 2) * PADW + kd];
            float a3 = Qs[(r0 + 3) * PADW + kd];
            float b0 = Ks[(c0 + 0) * PADW + kd];
            float b1 = Ks[(c0 + 1) * PADW + kd];
            float b2 = Ks[(c0 + 2) * PADW + kd];
            float b3 = Ks[(c0 + 3) * PADW + kd];
            s[0][0] += a0 * b0; s[0][1] += a0 * b1; s[0][2] += a0 * b2; s[0][3] += a0 * b3;
            s[1][0] += a1 * b0; s[1][1] += a1 * b1; s[1][2] += a1 * b2; s[1][3] += a1 * b3;
            s[2][0] += a2 * b0; s[2][1] += a2 * b1; s[2][2] += a2 * b2; s[2][3] += a2 * b3;
            s[3][0] += a3 * b0; s[3][1] += a3 * b1; s[3][2] += a3 * b2; s[3][3] += a3 * b3;
        }

        // mask + row max
        float mt[4];
#pragma unroll
        for (int i = 0; i < 4; i++) {
            int gi = q0 + r0 + i;
            float mm = -1e30f;
#pragma unroll
            for (int jj = 0; jj < 4; jj++) {
                int gj = j0 + c0 + jj;
                int dist = gi - gj;
                bool bad = (dist < 0) || (dist > WIN);
                float val = bad ? -1e30f : s[i][jj];
                s[i][jj] = val;
                mm = fmaxf(mm, val);
            }
            mt[i] = mm;
        }
#pragma unroll
        for (int off = 1; off < 16; off <<= 1)
#pragma unroll
            for (int i = 0; i < 4; i++)
                mt[i] = fmaxf(mt[i], __shfl_xor_sync(0xffffffffu, mt[i], off));

        float fac[4], rs[4];
#pragma unroll
        for (int i = 0; i < 4; i++) {
            float mnew = fmaxf(m_i[i], mt[i]);
            fac[i] = __expf(m_i[i] - mnew);
            m_i[i] = mnew;
            float su = 0.f;
#pragma unroll
            for (int jj = 0; jj < 4; jj++) {
                float p = __expf(s[i][jj] - mnew);
                s[i][jj] = p;
                su += p;
            }
            rs[i] = su;
        }
#pragma unroll
        for (int off = 1; off < 16; off <<= 1)
#pragma unroll
            for (int i = 0; i < 4; i++)
                rs[i] += __shfl_xor_sync(0xffffffffu, rs[i], off);
#pragma unroll
        for (int i = 0; i < 4; i++) {
            l_i[i] = l_i[i] * fac[i] + rs[i];
#pragma unroll
            for (int j = 0; j < 4; j++) o[i][j] *= fac[i];
        }

        // stage P
#pragma unroll
        for (int i = 0; i < 4; i++)
#pragma unroll
            for (int jj = 0; jj < 4; jj++)
                Ps[(r0 + i) * PADW + c0 + jj] = s[i][jj];
        __syncthreads();

        // O += P @ V
        for (int kk = 0; kk < 64; kk++) {
            float p0 = Ps[(r0 + 0) * PADW + kk];
            float p1 = Ps[(r0 + 1) * PADW + kk];
            float p2 = Ps[(r0 + 2) * PADW + kk];
            float p3 = Ps[(r0 + 3) * PADW + kk];
            float v0 = Vs[kk * PADW + c0 + 0];
            float v1 = Vs[kk * PADW + c0 + 1];
            float v2 = Vs[kk * PADW + c0 + 2];
            float v3 = Vs[kk * PADW + c0 + 3];
            o[0][0] += p0 * v0; o[0][1] += p0 * v1; o[0][2] += p0 * v2; o[0][3] += p0 * v3;
            o[1][0] += p1 * v0; o[1][1] += p1 * v1; o[1][2] += p1 * v2; o[1][3] += p1 * v3;
            o[2][0] += p2 * v0; o[2][1] += p2 * v1; o[2][2] += p2 * v2; o[2][3] += p2 * v3;
            o[3][0] += p3 * v0; o[3][1] += p3 * v1; o[3][2] += p3 * v2; o[3][3] += p3 * v3;
        }
        __syncthreads();
    }

    // epilogue: /l, *gate, write token-major
    float* ob = out + (size_t)b * Sn * HDn + h * Dn;
#pragma unroll
    for (int i = 0; i < 4; i++) {
        int gi = q0 + r0 + i;
        float g  = gate[((size_t)b * Sn + gi) * Hn + h];
        float sc = g / l_i[i];
        float4 w = make_float4(o[i][0] * sc, o[i][1] * sc, o[i][2] * sc, o[i][3] * sc);
        *(float4*)(ob + (size_t)gi * HDn + c0) = w;
    }
}

// ---------------------------------------------------------------------------
extern "C" void kernel_launch(void* const* d_in, const int* in_sizes, int n_in,
                              void* d_out, int out_size)
{
    const float* tokens = (const float*)d_in[0];
    const float* vres   = (const float*)d_in[1];
    const float* Wq     = (const float*)d_in[2];
    const float* Wkv    = (const float*)d_in[3];
    const float* Wout   = (const float*)d_in[4];
    const float* Wgate  = (const float*)d_in[5];
    const float* Wmix   = (const float*)d_in[6];
    float* out = (float*)d_out;

    float *pq, *pk, *pv, *pao, *pmix, *pgate;
    cudaGetSymbolAddress((void**)&pq,   g_q);
    cudaGetSymbolAddress((void**)&pk,   g_k);
    cudaGetSymbolAddress((void**)&pv,   g_v);
    cudaGetSymbolAddress((void**)&pao,  g_ao);
    cudaGetSymbolAddress((void**)&pmix, g_mix);
    cudaGetSymbolAddress((void**)&pgate,g_gate);

    // 1. Q projection
    sgemm128<<<dim3(8, 64), 256>>>(tokens, Wq, pq, pq, 1024, 1024);
    // 2. KV projection (cols 0..1023 -> k, 1024..2047 -> v)
    sgemm128<<<dim3(16, 64), 256>>>(tokens, Wkv, pk, pv, 1024, 2048);
    // 3. mix / gate logits + sigmoid
    mixgate<<<64, 256>>>(tokens, Wmix, Wgate, pmix, pgate);
    // 4. RoPE (q scaled) + k
    rope_qk<<<(Tn * Hn * 32) / 256, 256>>>(pq, pk);
    // 5. v lerp with residual
    vmix<<<(Tn * HDn) / 256, 256>>>(pv, vres, pmix);
    // 6. windowed attention (+gate)
    {
        int smem = 4 * 64 * PADW * (int)sizeof(float);
        cudaFuncSetAttribute(attn_win, cudaFuncAttributeMaxDynamicSharedMemorySize, smem);
        attn_win<<<dim3(Sn / 64, Hn, Bn), 256, smem>>>(pq, pk, pv, pgate, pao);
    }
    // 7. output projection straight into d_out
    sgemm128<<<dim3(8, 64), 256>>>(pao, Wout, out, out, 1024, 1024);
}

// round 3
// speedup vs baseline: 1.6079x; 1.6079x over previous
#include <cuda_runtime.h>
#include <cuda_bf16.h>
#include <math.h>
#include <stdint.h>

// Problem constants
#define Bn 4
#define Sn 2048
#define DIMn 1024
#define Hn 16
#define Dn 64
#define Tn (Bn*Sn)      // 8192 tokens
#define HDn 1024
#define WIN 512

// ---------------------------------------------------------------------------
// Scratch (device globals; no allocation allowed anywhere)
// ---------------------------------------------------------------------------
__device__ float g_q[(size_t)Tn*HDn];
__device__ float g_k[(size_t)Tn*HDn];
__device__ float g_v[(size_t)Tn*HDn];
__device__ float g_ao[(size_t)Tn*HDn];
__device__ float g_mix[Tn*Hn];
__device__ float g_gate[Tn*Hn];

// bf16 hi/lo splits
__device__ unsigned short g_tokh[(size_t)Tn*DIMn];
__device__ unsigned short g_tokl[(size_t)Tn*DIMn];
__device__ unsigned short g_aoh[(size_t)Tn*HDn];
__device__ unsigned short g_aol[(size_t)Tn*HDn];
__device__ unsigned short g_wqh[1024*1024];
__device__ unsigned short g_wql[1024*1024];
__device__ unsigned short g_wkvh[2048*1024];
__device__ unsigned short g_wkvl[2048*1024];
__device__ unsigned short g_woh[1024*1024];
__device__ unsigned short g_wol[1024*1024];

// ---------------------------------------------------------------------------
// Helpers: ldmatrix + mma.sync (base sm_103 target — NO tcgen05)
// ---------------------------------------------------------------------------
__device__ __forceinline__ uint32_t smem_u32(const void* p) {
    uint32_t a;
    asm("{ .reg .u64 t; cvta.to.shared.u64 t, %1; cvt.u32.u64 %0, t; }" : "=r"(a) : "l"(p));
    return a;
}
__device__ __forceinline__ void ldsm4(uint32_t* r, uint32_t addr) {
    asm volatile("ldmatrix.sync.aligned.m8n8.x4.shared.b16 {%0,%1,%2,%3}, [%4];"
                 : "=r"(r[0]), "=r"(r[1]), "=r"(r[2]), "=r"(r[3]) : "r"(addr));
}
__device__ __forceinline__ void mma16816(float* d, const uint32_t* a, const uint32_t* b) {
    asm volatile("mma.sync.aligned.m16n8k16.row.col.f32.bf16.bf16.f32 "
                 "{%0,%1,%2,%3},{%4,%5,%6,%7},{%8,%9},{%0,%1,%2,%3};"
                 : "+f"(d[0]), "+f"(d[1]), "+f"(d[2]), "+f"(d[3])
                 : "r"(a[0]), "r"(a[1]), "r"(a[2]), "r"(a[3]),
                   "r"(b[0]), "r"(b[1]));
}

// ---------------------------------------------------------------------------
// fp32 -> bf16 hi/lo split (elementwise)
// ---------------------------------------------------------------------------
__global__ void convA(const float* __restrict__ x, unsigned short* __restrict__ h,
                      unsigned short* __restrict__ l, int n4)
{
    int i = blockIdx.x * blockDim.x + threadIdx.x;
    if (i >= n4) return;
    float4 v = ((const float4*)x)[i];
    float vs[4] = {v.x, v.y, v.z, v.w};
    unsigned short hs[4], ls[4];
#pragma unroll
    for (int j = 0; j < 4; j++) {
        __nv_bfloat16 hb = __float2bfloat16_rn(vs[j]);
        float r = vs[j] - __bfloat162float(hb);
        __nv_bfloat16 lb = __float2bfloat16_rn(r);
        hs[j] = *reinterpret_cast<unsigned short*>(&hb);
        ls[j] = *reinterpret_cast<unsigned short*>(&lb);
    }
    ((ushort4*)h)[i] = make_ushort4(hs[0], hs[1], hs[2], hs[3]);
    ((ushort4*)l)[i] = make_ushort4(ls[0], ls[1], ls[2], ls[3]);
}

// W [K,N] fp32 -> Wt_hi/lo [N,K] bf16 (transpose via smem)
__global__ void convW(const float* __restrict__ W, unsigned short* __restrict__ Th,
                      unsigned short* __restrict__ Tl, int K, int N)
{
    __shared__ float t[32][33];
    int n0 = blockIdx.x * 32, k0 = blockIdx.y * 32;
    int tx = threadIdx.x, ty = threadIdx.y;   // blockDim (32, 8)
#pragma unroll
    for (int r = 0; r < 4; r++)
        t[ty + 8 * r][tx] = W[(size_t)(k0 + ty + 8 * r) * N + n0 + tx];
    __syncthreads();
#pragma unroll
    for (int r = 0; r < 4; r++) {
        float v = t[tx][ty + 8 * r];
        __nv_bfloat16 hb = __float2bfloat16_rn(v);
        float res = v - __bfloat162float(hb);
        __nv_bfloat16 lb = __float2bfloat16_rn(res);
        size_t o = (size_t)(n0 + ty + 8 * r) * K + k0 + tx;
        Th[o] = *reinterpret_cast<unsigned short*>(&hb);
        Tl[o] = *reinterpret_cast<unsigned short*>(&lb);
    }
}

// ---------------------------------------------------------------------------
// HMMA bf16x3 GEMM: C[M, 1024-strided] = A[M,1024] @ B^T  (B stored [N,1024])
// CTA 128x128, 8 warps (4m x 2n), warp tile 32x64, K-chunk 32, double buffer.
// ---------------------------------------------------------------------------
#define PADE 40                       // smem row: 32 data + 8 pad bf16 (80B)
#define TILE_ELEMS (128*PADE)
#define GEMM_SMEM (2*4*TILE_ELEMS*2)  // 81920 bytes

__global__ void __launch_bounds__(256) gemm_mma(
    const unsigned short* __restrict__ Ah, const unsigned short* __restrict__ Al,
    const unsigned short* __restrict__ Bh, const unsigned short* __restrict__ Bl,
    float* __restrict__ C0, float* __restrict__ C1)
{
    extern __shared__ unsigned short sh[];  // [buf][kind: Ah,Al,Bh,Bl][TILE_ELEMS]
    const int tid  = threadIdx.x;
    const int wid  = tid >> 5, lane = tid & 31;
    const int brow = blockIdx.y * 128, bcol = blockIdx.x * 128;
    const int wm   = (wid & 3) * 32;
    const int wn   = (wid >> 2) * 64;
    const int K    = 1024;

    const uint32_t sbase = smem_u32(sh);

    float acc[2][8][4];
#pragma unroll
    for (int i = 0; i < 2; i++)
#pragma unroll
        for (int j = 0; j < 8; j++)
#pragma unroll
            for (int k = 0; k < 4; k++) acc[i][j][k] = 0.f;

    const unsigned short* srcs[4] = {Ah, Al, Bh, Bl};
    const int rbase[4] = {brow, brow, bcol, bcol};

    auto load_chunk = [&](int k0, int buf) {
        unsigned short* dst = sh + buf * 4 * TILE_ELEMS;
#pragma unroll
        for (int kind = 0; kind < 4; kind++) {
#pragma unroll
            for (int i = 0; i < 2; i++) {
                int e = tid + i * 256;
                int row = e >> 2, ce = (e & 3) * 8;
                uint4 v = *(const uint4*)(srcs[kind] + (size_t)(rbase[kind] + row) * K + k0 + ce);
                *(uint4*)(dst + kind * TILE_ELEMS + row * PADE + ce) = v;
            }
        }
    };

    load_chunk(0, 0);
    __syncthreads();

    for (int c = 0; c < 32; c++) {
        int buf = c & 1;
        if (c + 1 < 32) load_chunk((c + 1) * 32, buf ^ 1);

        uint32_t abase = sbase + buf * 4 * TILE_ELEMS * 2;

#pragma unroll
        for (int ksub = 0; ksub < 2; ksub++) {
            // A fragments: [split][msub][4]
            uint32_t a[2][2][4];
            {
                int arow = wm + (lane & 15);
                int acol = ksub * 16 + (lane >> 4) * 8;
#pragma unroll
                for (int sp = 0; sp < 2; sp++)
#pragma unroll
                    for (int ms = 0; ms < 2; ms++)
                        ldsm4(a[sp][ms], abase + sp * TILE_ELEMS * 2 +
                              ((arow + ms * 16) * PADE + acol) * 2);
            }
            // B fragments: [split][nfrag][2]
            uint32_t b[2][8][2];
            {
                int bn = (lane & 7) | ((lane >> 1) & 8);
                int bk = ksub * 16 + ((lane >> 3) & 1) * 8;
#pragma unroll
                for (int sp = 0; sp < 2; sp++)
#pragma unroll
                    for (int g = 0; g < 4; g++) {
                        uint32_t r[4];
                        ldsm4(r, abase + (2 + sp) * TILE_ELEMS * 2 +
                              ((wn + g * 16 + bn) * PADE + bk) * 2);
                        b[sp][2 * g][0]     = r[0]; b[sp][2 * g][1]     = r[1];
                        b[sp][2 * g + 1][0] = r[2]; b[sp][2 * g + 1][1] = r[3];
                    }
            }
#pragma unroll
            for (int ms = 0; ms < 2; ms++)
#pragma unroll
                for (int nf = 0; nf < 8; nf++) {
                    mma16816(acc[ms][nf], a[0][ms], b[0][nf]);   // hi*hi
                    mma16816(acc[ms][nf], a[0][ms], b[1][nf]);   // hi*lo
                    mma16816(acc[ms][nf], a[1][ms], b[0][nf]);   // lo*hi
                }
        }
        __syncthreads();
    }

    // epilogue (whole CTA column block lies on one side of the 1024 split)
    float* Cb; int cbase;
    if (bcol < 1024) { Cb = C0; cbase = bcol; }
    else             { Cb = C1; cbase = bcol - 1024; }

#pragma unroll
    for (int ms = 0; ms < 2; ms++) {
        int r0 = brow + wm + ms * 16 + (lane >> 2);
#pragma unroll
        for (int nf = 0; nf < 8; nf++) {
            int cc = cbase + wn + nf * 8 + 2 * (lane & 3);
            *(float2*)(Cb + (size_t)r0 * 1024 + cc)       = make_float2(acc[ms][nf][0], acc[ms][nf][1]);
            *(float2*)(Cb + (size_t)(r0 + 8) * 1024 + cc) = make_float2(acc[ms][nf][2], acc[ms][nf][3]);
        }
    }
}

// ---------------------------------------------------------------------------
// mix/gate: (8192 x 1024) @ [Wmix | Wgate] (1024 x 32), sigmoid epilogue.
// ---------------------------------------------------------------------------
__global__ void __launch_bounds__(256) mixgate(
    const float* __restrict__ tokens, const float* __restrict__ Wmix,
    const float* __restrict__ Wgate, float* __restrict__ gmix,
    float* __restrict__ ggate)
{
    __shared__ float Ts[128][65];
    __shared__ float Ws[64][32];

    const int tid  = threadIdx.x;
    const int row0 = blockIdx.x * 128;
    const int r  = tid >> 1;
    const int cg = (tid & 1) << 4;

    float acc[16];
#pragma unroll
    for (int c = 0; c < 16; c++) acc[c] = 0.f;

    for (int k0 = 0; k0 < 1024; k0 += 64) {
#pragma unroll
        for (int u = 0; u < 8; u++) {
            int fi = tid + u * 256;
            int rr = fi >> 4;
            int cc = (fi & 15) << 2;
            float4 x = *(const float4*)(tokens + (size_t)(row0 + rr) * 1024 + k0 + cc);
            Ts[rr][cc] = x.x; Ts[rr][cc + 1] = x.y; Ts[rr][cc + 2] = x.z; Ts[rr][cc + 3] = x.w;
        }
#pragma unroll
        for (int u = 0; u < 8; u++) {
            int fi = tid + u * 256;
            int rr = fi >> 5;
            int cc = fi & 31;
            Ws[rr][cc] = (cc < 16) ? Wmix[(k0 + rr) * 16 + cc]
                                   : Wgate[(k0 + rr) * 16 + (cc - 16)];
        }
        __syncthreads();
        for (int kk = 0; kk < 64; kk++) {
            float a = Ts[r][kk];
#pragma unroll
            for (int c = 0; c < 16; c++) acc[c] += a * Ws[kk][cg + c];
        }
        __syncthreads();
    }

    const int t = row0 + r;
#pragma unroll
    for (int c = 0; c < 16; c++) {
        float sg = 1.0f / (1.0f + expf(-acc[c]));
        int col = cg + c;
        if (col < 16) gmix[t * 16 + col] = sg;
        else          ggate[t * 16 + (col - 16)] = sg;
    }
}

// ---------------------------------------------------------------------------
// Interleaved RoPE on q (with 1/sqrt(D) scale) and k.
// ---------------------------------------------------------------------------
__global__ void rope_qk(float* __restrict__ q, float* __restrict__ k)
{
    int idx = blockIdx.x * blockDim.x + threadIdx.x;
    if (idx >= Tn * Hn * 32) return;
    int i = idx & 31;
    int h = (idx >> 5) & 15;
    int t = idx >> 9;
    int s = t & (Sn - 1);

    float inv = powf(10000.0f, -(float)(2 * i) * (1.0f / 64.0f));
    float ang = (float)s * inv;
    float sn, cs;
    sincosf(ang, &sn, &cs);

    size_t base = (size_t)t * HDn + h * Dn + 2 * i;
    const float scale = 0.125f;
    float x0 = q[base], x1 = q[base + 1];
    q[base]     = (x0 * cs - x1 * sn) * scale;
    q[base + 1] = (x1 * cs + x0 * sn) * scale;
    x0 = k[base]; x1 = k[base + 1];
    k[base]     = x0 * cs - x1 * sn;
    k[base + 1] = x1 * cs + x0 * sn;
}

// ---------------------------------------------------------------------------
// v = v + (value_residual - v) * mix
// ---------------------------------------------------------------------------
__global__ void vmix(float* __restrict__ v, const float* __restrict__ vr,
                     const float* __restrict__ mix)
{
    int idx = blockIdx.x * blockDim.x + threadIdx.x;
    if (idx >= Tn * HDn) return;
    int d = idx & 63;
    int h = (idx >> 6) & 15;
    int t = idx >> 10;
    int s = t & (Sn - 1);
    int b = t >> 11;
    float m  = mix[t * Hn + h];
    float vv = v[idx];
    float rr = vr[(((size_t)b * Hn + h) * Sn + s) * Dn + d];
    v[idx] = vv + (rr - vv) * m;
}

// ---------------------------------------------------------------------------
// Sliding-window flash attention (fp32), 64-row query tiles.
// ---------------------------------------------------------------------------
#define PADW 65
__global__ void __launch_bounds__(256) attn_win(
    const float* __restrict__ q, const float* __restrict__ k,
    const float* __restrict__ v, const float* __restrict__ gate,
    float* __restrict__ out)
{
    extern __shared__ float sm[];
    float* Qs = sm;
    float* Ks = sm + 64 * PADW;
    float* Vs = sm + 2 * 64 * PADW;
    float* Ps = sm + 3 * 64 * PADW;

    const int b  = blockIdx.z;
    const int h  = blockIdx.y;
    const int q0 = blockIdx.x * 64;
    const int tid = threadIdx.x;
    const int ty = tid >> 4, tx = tid & 15;
    const int r0 = ty << 2, c0 = tx << 2;

    const float* qb = q + (size_t)b * Sn * HDn + h * Dn;
    const float* kb = k + (size_t)b * Sn * HDn + h * Dn;
    const float* vb = v + (size_t)b * Sn * HDn + h * Dn;

    {
        int r  = tid >> 2;
        int cc = (tid & 3) << 4;
        const float* src = qb + (size_t)(q0 + r) * HDn + cc;
        float* dst = Qs + r * PADW + cc;
#pragma unroll
        for (int u = 0; u < 4; u++) {
            float4 x = *(const float4*)(src + 4 * u);
            dst[4 * u] = x.x; dst[4 * u + 1] = x.y; dst[4 * u + 2] = x.z; dst[4 * u + 3] = x.w;
        }
    }

    float m_i[4], l_i[4], o[4][4];
#pragma unroll
    for (int i = 0; i < 4; i++) {
        m_i[i] = -1e30f; l_i[i] = 0.f;
#pragma unroll
        for (int j = 0; j < 4; j++) o[i][j] = 0.f;
    }

    int jt_lo = (q0 >= WIN) ? ((q0 - WIN) >> 6) : 0;
    int jt_hi = q0 >> 6;

    for (int jt = jt_lo; jt <= jt_hi; jt++) {
        int j0 = jt << 6;
        {
            int r  = tid >> 2;
            int cc = (tid & 3) << 4;
            const float* ksrc = kb + (size_t)(j0 + r) * HDn + cc;
            const float* vsrc = vb + (size_t)(j0 + r) * HDn + cc;
            float* kd = Ks + r * PADW + cc;
            float* vd = Vs + r * PADW + cc;
#pragma unroll
            for (int u = 0; u < 4; u++) {
                float4 x = *(const float4*)(ksrc + 4 * u);
                kd[4 * u] = x.x; kd[4 * u + 1] = x.y; kd[4 * u + 2] = x.z; kd[4 * u + 3] = x.w;
                float4 y = *(const float4*)(vsrc + 4 * u);
                vd[4 * u] = y.x; vd[4 * u + 1] = y.y; vd[4 * u + 2] = y.z; vd[4 * u + 3] = y.w;
            }
        }
        __syncthreads();

        float s[4][4];
#pragma unroll
        for (int i = 0; i < 4; i++)
#pragma unroll
            for (int j = 0; j < 4; j++) s[i][j] = 0.f;

        for (int kd = 0; kd < 64; kd++) {
            float a0 = Qs[(r0 + 0) * PADW + kd];
            float a1 = Qs[(r0 + 1) * PADW + kd];
            float a2 = Qs[(r0 + 2) * PADW + kd];
            float a3 = Qs[(r0 + 3) * PADW + kd];
            float b0 = Ks[(c0 + 0) * PADW + kd];
            float b1 = Ks[(c0 + 1) * PADW + kd];
            float b2 = Ks[(c0 + 2) * PADW + kd];
            float b3 = Ks[(c0 + 3) * PADW + kd];
            s[0][0] += a0 * b0; s[0][1] += a0 * b1; s[0][2] += a0 * b2; s[0][3] += a0 * b3;
            s[1][0] += a1 * b0; s[1][1] += a1 * b1; s[1][2] += a1 * b2; s[1][3] += a1 * b3;
            s[2][0] += a2 * b0; s[2][1] += a2 * b1; s[2][2] += a2 * b2; s[2][3] += a2 * b3;
            s[3][0] += a3 * b0; s[3][1] += a3 * b1; s[3][2] += a3 * b2; s[3][3] += a3 * b3;
        }

        float mt[4];
#pragma unroll
        for (int i = 0; i < 4; i++) {
            int gi = q0 + r0 + i;
            float mm = -1e30f;
#pragma unroll
            for (int jj = 0; jj < 4; jj++) {
                int gj = j0 + c0 + jj;
                int dist = gi - gj;
                bool bad = (dist < 0) || (dist > WIN);
                float val = bad ? -1e30f : s[i][jj];
                s[i][jj] = val;
                mm = fmaxf(mm, val);
            }
            mt[i] = mm;
        }
#pragma unroll
        for (int off = 1; off < 16; off <<= 1)
#pragma unroll
            for (int i = 0; i < 4; i++)
                mt[i] = fmaxf(mt[i], __shfl_xor_sync(0xffffffffu, mt[i], off));

        float fac[4], rs[4];
#pragma unroll
        for (int i = 0; i < 4; i++) {
            float mnew = fmaxf(m_i[i], mt[i]);
            fac[i] = __expf(m_i[i] - mnew);
            m_i[i] = mnew;
            float su = 0.f;
#pragma unroll
            for (int jj = 0; jj < 4; jj++) {
                float p = __expf(s[i][jj] - mnew);
                s[i][jj] = p;
                su += p;
            }
            rs[i] = su;
        }
#pragma unroll
        for (int off = 1; off < 16; off <<= 1)
#pragma unroll
            for (int i = 0; i < 4; i++)
                rs[i] += __shfl_xor_sync(0xffffffffu, rs[i], off);
#pragma unroll
        for (int i = 0; i < 4; i++) {
            l_i[i] = l_i[i] * fac[i] + rs[i];
#pragma unroll
            for (int j = 0; j < 4; j++) o[i][j] *= fac[i];
        }

#pragma unroll
        for (int i = 0; i < 4; i++)
#pragma unroll
            for (int jj = 0; jj < 4; jj++)
                Ps[(r0 + i) * PADW + c0 + jj] = s[i][jj];
        __syncthreads();

        for (int kk = 0; kk < 64; kk++) {
            float p0 = Ps[(r0 + 0) * PADW + kk];
            float p1 = Ps[(r0 + 1) * PADW + kk];
            float p2 = Ps[(r0 + 2) * PADW + kk];
            float p3 = Ps[(r0 + 3) * PADW + kk];
            float v0 = Vs[kk * PADW + c0 + 0];
            float v1 = Vs[kk * PADW + c0 + 1];
            float v2 = Vs[kk * PADW + c0 + 2];
            float v3 = Vs[kk * PADW + c0 + 3];
            o[0][0] += p0 * v0; o[0][1] += p0 * v1; o[0][2] += p0 * v2; o[0][3] += p0 * v3;
            o[1][0] += p1 * v0; o[1][1] += p1 * v1; o[1][2] += p1 * v2; o[1][3] += p1 * v3;
            o[2][0] += p2 * v0; o[2][1] += p2 * v1; o[2][2] += p2 * v2; o[2][3] += p2 * v3;
            o[3][0] += p3 * v0; o[3][1] += p3 * v1; o[3][2] += p3 * v2; o[3][3] += p3 * v3;
        }
        __syncthreads();
    }

    float* ob = out + (size_t)b * Sn * HDn + h * Dn;
#pragma unroll
    for (int i = 0; i < 4; i++) {
        int gi = q0 + r0 + i;
        float g  = gate[((size_t)b * Sn + gi) * Hn + h];
        float sc = g / l_i[i];
        float4 w = make_float4(o[i][0] * sc, o[i][1] * sc, o[i][2] * sc, o[i][3] * sc);
        *(float4*)(ob + (size_t)gi * HDn + c0) = w;
    }
}

// ---------------------------------------------------------------------------
extern "C" void kernel_launch(void* const* d_in, const int* in_sizes, int n_in,
                              void* d_out, int out_size)
{
    const float* tokens = (const float*)d_in[0];
    const float* vres   = (const float*)d_in[1];
    const float* Wq     = (const float*)d_in[2];
    const float* Wkv    = (const float*)d_in[3];
    const float* Wout   = (const float*)d_in[4];
    const float* Wgate  = (const float*)d_in[5];
    const float* Wmix   = (const float*)d_in[6];
    float* out = (float*)d_out;

    float *pq, *pk, *pv, *pao, *pmix, *pgate;
    unsigned short *tkh, *tkl, *aoh, *aol, *wqh, *wql, *wkvh, *wkvl, *woh, *wol;
    cudaGetSymbolAddress((void**)&pq,   g_q);
    cudaGetSymbolAddress((void**)&pk,   g_k);
    cudaGetSymbolAddress((void**)&pv,   g_v);
    cudaGetSymbolAddress((void**)&pao,  g_ao);
    cudaGetSymbolAddress((void**)&pmix, g_mix);
    cudaGetSymbolAddress((void**)&pgate,g_gate);
    cudaGetSymbolAddress((void**)&tkh,  g_tokh);
    cudaGetSymbolAddress((void**)&tkl,  g_tokl);
    cudaGetSymbolAddress((void**)&aoh,  g_aoh);
    cudaGetSymbolAddress((void**)&aol,  g_aol);
    cudaGetSymbolAddress((void**)&wqh,  g_wqh);
    cudaGetSymbolAddress((void**)&wql,  g_wql);
    cudaGetSymbolAddress((void**)&wkvh, g_wkvh);
    cudaGetSymbolAddress((void**)&wkvl, g_wkvl);
    cudaGetSymbolAddress((void**)&woh,  g_woh);
    cudaGetSymbolAddress((void**)&wol,  g_wol);

    cudaFuncSetAttribute(gemm_mma, cudaFuncAttributeMaxDynamicSharedMemorySize, GEMM_SMEM);

    // 1. split tokens and weights into bf16 hi/lo
    convA<<<(Tn * DIMn / 4 + 255) / 256, 256>>>(tokens, tkh, tkl, Tn * DIMn / 4);
    convW<<<dim3(1024 / 32, 1024 / 32), dim3(32, 8)>>>(Wq,   wqh,  wql,  1024, 1024);
    convW<<<dim3(2048 / 32, 1024 / 32), dim3(32, 8)>>>(Wkv,  wkvh, wkvl, 1024, 2048);
    convW<<<dim3(1024 / 32, 1024 / 32), dim3(32, 8)>>>(Wout, woh,  wol,  1024, 1024);

    // 2. Q and KV projections on tensor cores (bf16x3 via mma.sync)
    gemm_mma<<<dim3(8,  64), 256, GEMM_SMEM>>>(tkh, tkl, wqh,  wql,  pq, pq);
    gemm_mma<<<dim3(16, 64), 256, GEMM_SMEM>>>(tkh, tkl, wkvh, wkvl, pk, pv);

    // 3. mix / gate logits + sigmoid
    mixgate<<<64, 256>>>(tokens, Wmix, Wgate, pmix, pgate);
    // 4. RoPE (q scaled) + k
    rope_qk<<<(Tn * Hn * 32) / 256, 256>>>(pq, pk);
    // 5. v lerp with residual
    vmix<<<(Tn * HDn) / 256, 256>>>(pv, vres, pmix);
    // 6. windowed attention (+gate)
    {
        int smem = 4 * 64 * PADW * (int)sizeof(float);
        cudaFuncSetAttribute(attn_win, cudaFuncAttributeMaxDynamicSharedMemorySize, smem);
        attn_win<<<dim3(Sn / 64, Hn, Bn), 256, smem>>>(pq, pk, pv, pgate, pao);
    }
    // 7. split attention output, project into d_out
    convA<<<(Tn * HDn / 4 + 255) / 256, 256>>>(pao, aoh, aol, Tn * HDn / 4);
    gemm_mma<<<dim3(8, 64), 256, GEMM_SMEM>>>(aoh, aol, woh, wol, out, out);
}

// round 4
// speedup vs baseline: 2.3526x; 1.4632x over previous
#include <cuda_runtime.h>
#include <cuda_bf16.h>
#include <math.h>
#include <stdint.h>

// Problem constants
#define Bn 4
#define Sn 2048
#define DIMn 1024
#define Hn 16
#define Dn 64
#define Tn (Bn*Sn)      // 8192 tokens
#define HDn 1024
#define WIN 512

typedef unsigned short ush;

// ---------------------------------------------------------------------------
// Scratch (device globals)
// ---------------------------------------------------------------------------
__device__ float g_q[(size_t)Tn*HDn];
__device__ float g_k[(size_t)Tn*HDn];
__device__ float g_v[(size_t)Tn*HDn];
__device__ float g_mix[Tn*Hn];
__device__ float g_gate[Tn*Hn];

__device__ ush g_tokh[(size_t)Tn*DIMn];
__device__ ush g_tokl[(size_t)Tn*DIMn];
__device__ ush g_aoh[(size_t)Tn*HDn];
__device__ ush g_aol[(size_t)Tn*HDn];
__device__ ush g_wqh[1024*1024];
__device__ ush g_wql[1024*1024];
__device__ ush g_wkvh[2048*1024];
__device__ ush g_wkvl[2048*1024];
__device__ ush g_woh[1024*1024];
__device__ ush g_wol[1024*1024];
// post-rope / post-vmix bf16 splits
__device__ ush g_qsh[(size_t)Tn*HDn];
__device__ ush g_qsl[(size_t)Tn*HDn];
__device__ ush g_ksh[(size_t)Tn*HDn];
__device__ ush g_ksl[(size_t)Tn*HDn];
__device__ ush g_vsh[(size_t)Tn*HDn];
__device__ ush g_vsl[(size_t)Tn*HDn];

// ---------------------------------------------------------------------------
// Helpers (base sm_103 target — mma.sync / ldmatrix only, NO tcgen05)
// ---------------------------------------------------------------------------
__device__ __forceinline__ uint32_t smem_u32(const void* p) {
    uint32_t a;
    asm("{ .reg .u64 t; cvta.to.shared.u64 t, %1; cvt.u32.u64 %0, t; }" : "=r"(a) : "l"(p));
    return a;
}
__device__ __forceinline__ void ldsm4(uint32_t* r, uint32_t addr) {
    asm volatile("ldmatrix.sync.aligned.m8n8.x4.shared.b16 {%0,%1,%2,%3}, [%4];"
                 : "=r"(r[0]), "=r"(r[1]), "=r"(r[2]), "=r"(r[3]) : "r"(addr));
}
__device__ __forceinline__ void ldsm4t(uint32_t* r, uint32_t addr) {
    asm volatile("ldmatrix.sync.aligned.m8n8.x4.trans.shared.b16 {%0,%1,%2,%3}, [%4];"
                 : "=r"(r[0]), "=r"(r[1]), "=r"(r[2]), "=r"(r[3]) : "r"(addr));
}
__device__ __forceinline__ void mma16816(float* d, const uint32_t* a, const uint32_t* b) {
    asm volatile("mma.sync.aligned.m16n8k16.row.col.f32.bf16.bf16.f32 "
                 "{%0,%1,%2,%3},{%4,%5,%6,%7},{%8,%9},{%0,%1,%2,%3};"
                 : "+f"(d[0]), "+f"(d[1]), "+f"(d[2]), "+f"(d[3])
                 : "r"(a[0]), "r"(a[1]), "r"(a[2]), "r"(a[3]),
                   "r"(b[0]), "r"(b[1]));
}
// pack two fp32 -> bf16x2 (lo in low 16 bits)
__device__ __forceinline__ uint32_t packbf(float lo, float hi) {
    uint32_t r;
    asm("cvt.rn.bf16x2.f32 %0, %1, %2;" : "=r"(r) : "f"(hi), "f"(lo));
    return r;
}
__device__ __forceinline__ void split2(float x, ush& h, ush& l) {
    __nv_bfloat16 hb = __float2bfloat16_rn(x);
    float r = x - __bfloat162float(hb);
    __nv_bfloat16 lb = __float2bfloat16_rn(r);
    h = *reinterpret_cast<ush*>(&hb);
    l = *reinterpret_cast<ush*>(&lb);
}

// ---------------------------------------------------------------------------
// fp32 -> bf16 hi/lo split (elementwise)
// ---------------------------------------------------------------------------
__global__ void convA(const float* __restrict__ x, ush* __restrict__ h,
                      ush* __restrict__ l, int n4)
{
    int i = blockIdx.x * blockDim.x + threadIdx.x;
    if (i >= n4) return;
    float4 v = ((const float4*)x)[i];
    float vs[4] = {v.x, v.y, v.z, v.w};
    ush hs[4], ls[4];
#pragma unroll
    for (int j = 0; j < 4; j++) split2(vs[j], hs[j], ls[j]);
    ((ushort4*)h)[i] = make_ushort4(hs[0], hs[1], hs[2], hs[3]);
    ((ushort4*)l)[i] = make_ushort4(ls[0], ls[1], ls[2], ls[3]);
}

// W [K,N] fp32 -> Wt_hi/lo [N,K] bf16 (transpose via smem)
__global__ void convW(const float* __restrict__ W, ush* __restrict__ Th,
                      ush* __restrict__ Tl, int K, int N)
{
    __shared__ float t[32][33];
    int n0 = blockIdx.x * 32, k0 = blockIdx.y * 32;
    int tx = threadIdx.x, ty = threadIdx.y;   // blockDim (32, 8)
#pragma unroll
    for (int r = 0; r < 4; r++)
        t[ty + 8 * r][tx] = W[(size_t)(k0 + ty + 8 * r) * N + n0 + tx];
    __syncthreads();
#pragma unroll
    for (int r = 0; r < 4; r++) {
        float v = t[tx][ty + 8 * r];
        size_t o = (size_t)(n0 + ty + 8 * r) * K + k0 + tx;
        ush hh, ll;
        split2(v, hh, ll);
        Th[o] = hh; Tl[o] = ll;
    }
}

// ---------------------------------------------------------------------------
// HMMA bf16x3 GEMM: C[M, 1024-strided] = A[M,1024] @ B^T  (B stored [N,1024])
// CTA 128x128, 8 warps, warp tile 32x64, K-chunk 32, double buffer.
// ---------------------------------------------------------------------------
#define PADE 40
#define TILE_ELEMS (128*PADE)
#define GEMM_SMEM (2*4*TILE_ELEMS*2)

__global__ void __launch_bounds__(256) gemm_mma(
    const ush* __restrict__ Ah, const ush* __restrict__ Al,
    const ush* __restrict__ Bh, const ush* __restrict__ Bl,
    float* __restrict__ C0, float* __restrict__ C1)
{
    extern __shared__ ush sh[];
    const int tid  = threadIdx.x;
    const int wid  = tid >> 5, lane = tid & 31;
    const int brow = blockIdx.y * 128, bcol = blockIdx.x * 128;
    const int wm   = (wid & 3) * 32;
    const int wn   = (wid >> 2) * 64;
    const int K    = 1024;

    const uint32_t sbase = smem_u32(sh);

    float acc[2][8][4];
#pragma unroll
    for (int i = 0; i < 2; i++)
#pragma unroll
        for (int j = 0; j < 8; j++)
#pragma unroll
            for (int k = 0; k < 4; k++) acc[i][j][k] = 0.f;

    const ush* srcs[4] = {Ah, Al, Bh, Bl};
    const int rbase[4] = {brow, brow, bcol, bcol};

    auto load_chunk = [&](int k0, int buf) {
        ush* dst = sh + buf * 4 * TILE_ELEMS;
#pragma unroll
        for (int kind = 0; kind < 4; kind++) {
#pragma unroll
            for (int i = 0; i < 2; i++) {
                int e = tid + i * 256;
                int row = e >> 2, ce = (e & 3) * 8;
                uint4 v = *(const uint4*)(srcs[kind] + (size_t)(rbase[kind] + row) * K + k0 + ce);
                *(uint4*)(dst + kind * TILE_ELEMS + row * PADE + ce) = v;
            }
        }
    };

    load_chunk(0, 0);
    __syncthreads();

    for (int c = 0; c < 32; c++) {
        int buf = c & 1;
        if (c + 1 < 32) load_chunk((c + 1) * 32, buf ^ 1);

        uint32_t abase = sbase + buf * 4 * TILE_ELEMS * 2;

#pragma unroll
        for (int ksub = 0; ksub < 2; ksub++) {
            uint32_t a[2][2][4];
            {
                int arow = wm + (lane & 15);
                int acol = ksub * 16 + (lane >> 4) * 8;
#pragma unroll
                for (int sp = 0; sp < 2; sp++)
#pragma unroll
                    for (int ms = 0; ms < 2; ms++)
                        ldsm4(a[sp][ms], abase + sp * TILE_ELEMS * 2 +
                              ((arow + ms * 16) * PADE + acol) * 2);
            }
            uint32_t b[2][8][2];
            {
                int bn = (lane & 7) | ((lane >> 1) & 8);
                int bk = ksub * 16 + ((lane >> 3) & 1) * 8;
#pragma unroll
                for (int sp = 0; sp < 2; sp++)
#pragma unroll
                    for (int g = 0; g < 4; g++) {
                        uint32_t r[4];
                        ldsm4(r, abase + (2 + sp) * TILE_ELEMS * 2 +
                              ((wn + g * 16 + bn) * PADE + bk) * 2);
                        b[sp][2 * g][0]     = r[0]; b[sp][2 * g][1]     = r[1];
                        b[sp][2 * g + 1][0] = r[2]; b[sp][2 * g + 1][1] = r[3];
                    }
            }
#pragma unroll
            for (int ms = 0; ms < 2; ms++)
#pragma unroll
                for (int nf = 0; nf < 8; nf++) {
                    mma16816(acc[ms][nf], a[0][ms], b[0][nf]);
                    mma16816(acc[ms][nf], a[0][ms], b[1][nf]);
                    mma16816(acc[ms][nf], a[1][ms], b[0][nf]);
                }
        }
        __syncthreads();
    }

    float* Cb; int cbase;
    if (bcol < 1024) { Cb = C0; cbase = bcol; }
    else             { Cb = C1; cbase = bcol - 1024; }

#pragma unroll
    for (int ms = 0; ms < 2; ms++) {
        int r0 = brow + wm + ms * 16 + (lane >> 2);
#pragma unroll
        for (int nf = 0; nf < 8; nf++) {
            int cc = cbase + wn + nf * 8 + 2 * (lane & 3);
            *(float2*)(Cb + (size_t)r0 * 1024 + cc)       = make_float2(acc[ms][nf][0], acc[ms][nf][1]);
            *(float2*)(Cb + (size_t)(r0 + 8) * 1024 + cc) = make_float2(acc[ms][nf][2], acc[ms][nf][3]);
        }
    }
}

// ---------------------------------------------------------------------------
// mix/gate: (8192 x 1024) @ [Wmix | Wgate] (1024 x 32), sigmoid epilogue.
// ---------------------------------------------------------------------------
__global__ void __launch_bounds__(256) mixgate(
    const float* __restrict__ tokens, const float* __restrict__ Wmix,
    const float* __restrict__ Wgate, float* __restrict__ gmix,
    float* __restrict__ ggate)
{
    __shared__ float Ts[128][65];
    __shared__ float Ws[64][32];

    const int tid  = threadIdx.x;
    const int row0 = blockIdx.x * 128;
    const int r  = tid >> 1;
    const int cg = (tid & 1) << 4;

    float acc[16];
#pragma unroll
    for (int c = 0; c < 16; c++) acc[c] = 0.f;

    for (int k0 = 0; k0 < 1024; k0 += 64) {
#pragma unroll
        for (int u = 0; u < 8; u++) {
            int fi = tid + u * 256;
            int rr = fi >> 4;
            int cc = (fi & 15) << 2;
            float4 x = *(const float4*)(tokens + (size_t)(row0 + rr) * 1024 + k0 + cc);
            Ts[rr][cc] = x.x; Ts[rr][cc + 1] = x.y; Ts[rr][cc + 2] = x.z; Ts[rr][cc + 3] = x.w;
        }
#pragma unroll
        for (int u = 0; u < 8; u++) {
            int fi = tid + u * 256;
            int rr = fi >> 5;
            int cc = fi & 31;
            Ws[rr][cc] = (cc < 16) ? Wmix[(k0 + rr) * 16 + cc]
                                   : Wgate[(k0 + rr) * 16 + (cc - 16)];
        }
        __syncthreads();
        for (int kk = 0; kk < 64; kk++) {
            float a = Ts[r][kk];
#pragma unroll
            for (int c = 0; c < 16; c++) acc[c] += a * Ws[kk][cg + c];
        }
        __syncthreads();
    }

    const int t = row0 + r;
#pragma unroll
    for (int c = 0; c < 16; c++) {
        float sg = 1.0f / (1.0f + expf(-acc[c]));
        int col = cg + c;
        if (col < 16) gmix[t * 16 + col] = sg;
        else          ggate[t * 16 + (col - 16)] = sg;
    }
}

// ---------------------------------------------------------------------------
// RoPE on q (scaled) and k; outputs bf16 hi/lo splits.
// ---------------------------------------------------------------------------
__global__ void rope_qk(const float* __restrict__ q, const float* __restrict__ k,
                        ush* __restrict__ qh, ush* __restrict__ ql,
                        ush* __restrict__ kh, ush* __restrict__ kl)
{
    int idx = blockIdx.x * blockDim.x + threadIdx.x;   // Tn*Hn*32 pairs
    if (idx >= Tn * Hn * 32) return;
    int i = idx & 31;
    int h = (idx >> 5) & 15;
    int t = idx >> 9;
    int s = t & (Sn - 1);

    float inv = powf(10000.0f, -(float)(2 * i) * (1.0f / 64.0f));
    float ang = (float)s * inv;
    float sn, cs;
    sincosf(ang, &sn, &cs);

    size_t base = (size_t)t * HDn + h * Dn + 2 * i;
    const float scale = 0.125f;
    float x0 = q[base], x1 = q[base + 1];
    float q0 = (x0 * cs - x1 * sn) * scale;
    float q1 = (x1 * cs + x0 * sn) * scale;
    x0 = k[base]; x1 = k[base + 1];
    float k0 = x0 * cs - x1 * sn;
    float k1 = x1 * cs + x0 * sn;

    ush h0, l0, h1, l1;
    split2(q0, h0, l0); split2(q1, h1, l1);
    *(uint32_t*)(qh + base) = (uint32_t)h0 | ((uint32_t)h1 << 16);
    *(uint32_t*)(ql + base) = (uint32_t)l0 | ((uint32_t)l1 << 16);
    split2(k0, h0, l0); split2(k1, h1, l1);
    *(uint32_t*)(kh + base) = (uint32_t)h0 | ((uint32_t)h1 << 16);
    *(uint32_t*)(kl + base) = (uint32_t)l0 | ((uint32_t)l1 << 16);
}

// ---------------------------------------------------------------------------
// v = v + (value_residual - v) * mix ; outputs bf16 hi/lo splits.
// ---------------------------------------------------------------------------
__global__ void vmix(const float* __restrict__ v, const float* __restrict__ vr,
                     const float* __restrict__ mix,
                     ush* __restrict__ vh, ush* __restrict__ vl)
{
    int idx = blockIdx.x * blockDim.x + threadIdx.x;   // over Tn*HDn/2 pairs
    if (idx >= Tn * HDn / 2) return;
    int e = idx * 2;
    int d = e & 63;
    int h = (e >> 6) & 15;
    int t = e >> 10;
    int s = t & (Sn - 1);
    int b = t >> 11;
    float m  = mix[t * Hn + h];
    float2 vv = *(const float2*)(v + e);
    const float* rp = vr + (((size_t)b * Hn + h) * Sn + s) * Dn + d;
    float r0 = rp[0], r1 = rp[1];
    float o0 = vv.x + (r0 - vv.x) * m;
    float o1 = vv.y + (r1 - vv.y) * m;
    ush h0, l0, h1, l1;
    split2(o0, h0, l0); split2(o1, h1, l1);
    *(uint32_t*)(vh + e) = (uint32_t)h0 | ((uint32_t)h1 << 16);
    *(uint32_t*)(vl + e) = (uint32_t)l0 | ((uint32_t)l1 << 16);
}

// ---------------------------------------------------------------------------
// Sliding-window flash attention, HMMA bf16x3, online softmax in registers.
// CTA = (64-query tile, head, batch); 4 warps, warp = 16 rows x 64 keys.
// ---------------------------------------------------------------------------
#define APAD 72
#define ATT_SMEM (6*64*APAD*2)

__global__ void __launch_bounds__(128) attn_mma(
    const ush* __restrict__ qh, const ush* __restrict__ ql,
    const ush* __restrict__ kh, const ush* __restrict__ kl,
    const ush* __restrict__ vh, const ush* __restrict__ vl,
    const float* __restrict__ gate,
    ush* __restrict__ aoh, ush* __restrict__ aol)
{
    extern __shared__ ush smA[];
    ush* Qh = smA;
    ush* Ql = Qh + 64 * APAD;
    ush* Kh = Ql + 64 * APAD;
    ush* Kl = Kh + 64 * APAD;
    ush* Vh = Kl + 64 * APAD;
    ush* Vl = Vh + 64 * APAD;

    const int b = blockIdx.z, h = blockIdx.y, q0 = blockIdx.x * 64;
    const int tid = threadIdx.x, wid = tid >> 5, lane = tid & 31;
    const int wm = wid * 16;
    const size_t bbase = (size_t)b * Sn;
    const int hoff = h * Dn;

    // load Q tiles (once)
#pragma unroll
    for (int i = 0; i < 4; i++) {
        int e = tid + i * 128;
        int row = e >> 3, c = (e & 7) * 8;
        size_t g = (bbase + q0 + row) * (size_t)HDn + hoff + c;
        *(uint4*)(Qh + row * APAD + c) = *(const uint4*)(qh + g);
        *(uint4*)(Ql + row * APAD + c) = *(const uint4*)(ql + g);
    }
    __syncthreads();

    // hoist Q fragments
    uint32_t qfh[4][4], qfl[4][4];
    {
        uint32_t qb = smem_u32(Qh), qbl = smem_u32(Ql);
        int arow = wm + (lane & 15);
        int ac0  = (lane >> 4) * 8;
#pragma unroll
        for (int ks = 0; ks < 4; ks++) {
            ldsm4(qfh[ks], qb  + (arow * APAD + ks * 16 + ac0) * 2);
            ldsm4(qfl[ks], qbl + (arow * APAD + ks * 16 + ac0) * 2);
        }
    }

    float mi0 = -1e30f, mi1 = -1e30f, li0 = 0.f, li1 = 0.f;
    float accO[8][4];
#pragma unroll
    for (int i = 0; i < 8; i++)
#pragma unroll
        for (int j = 0; j < 4; j++) accO[i][j] = 0.f;

    const int jt_lo = (q0 >= WIN) ? ((q0 - WIN) >> 6) : 0;
    const int jt_hi = q0 >> 6;
    const int gi0 = q0 + wm + (lane >> 2);
    const int gi1 = gi0 + 8;

    const uint32_t kb  = smem_u32(Kh), kbl = smem_u32(Kl);
    const uint32_t vb  = smem_u32(Vh), vbl = smem_u32(Vl);
    const int bn  = (lane & 7) | ((lane >> 1) & 8);
    const int bk8 = ((lane >> 3) & 1) * 8;
    const int vr0 = lane & 15;
    const int vc8 = (lane >> 4) * 8;

    for (int jt = jt_lo; jt <= jt_hi; jt++) {
        const int j0 = jt * 64;
        // load K/V tiles
#pragma unroll
        for (int i = 0; i < 4; i++) {
            int e = tid + i * 128;
            int row = e >> 3, c = (e & 7) * 8;
            size_t g = (bbase + j0 + row) * (size_t)HDn + hoff + c;
            *(uint4*)(Kh + row * APAD + c) = *(const uint4*)(kh + g);
            *(uint4*)(Kl + row * APAD + c) = *(const uint4*)(kl + g);
            *(uint4*)(Vh + row * APAD + c) = *(const uint4*)(vh + g);
            *(uint4*)(Vl + row * APAD + c) = *(const uint4*)(vl + g);
        }
        __syncthreads();

        // S = Q K^T (bf16x3)
        float s[8][4];
#pragma unroll
        for (int i = 0; i < 8; i++)
#pragma unroll
            for (int j = 0; j < 4; j++) s[i][j] = 0.f;

#pragma unroll
        for (int ks = 0; ks < 4; ks++) {
#pragma unroll
            for (int g2 = 0; g2 < 4; g2++) {
                uint32_t off = (uint32_t)(((g2 * 16 + bn) * APAD + ks * 16 + bk8) * 2);
                uint32_t rh[4], rl[4];
                ldsm4(rh, kb  + off);
                ldsm4(rl, kbl + off);
                uint32_t bh0[2] = {rh[0], rh[1]}, bh1[2] = {rh[2], rh[3]};
                uint32_t bl0[2] = {rl[0], rl[1]}, bl1[2] = {rl[2], rl[3]};
                mma16816(s[2*g2],   qfh[ks], bh0);
                mma16816(s[2*g2],   qfh[ks], bl0);
                mma16816(s[2*g2],   qfl[ks], bh0);
                mma16816(s[2*g2+1], qfh[ks], bh1);
                mma16816(s[2*g2+1], qfh[ks], bl1);
                mma16816(s[2*g2+1], qfl[ks], bh1);
            }
        }

        // mask (only boundary tiles need it)
        if (jt == jt_hi || (jt == jt_lo && q0 >= WIN)) {
#pragma unroll
            for (int nf = 0; nf < 8; nf++) {
                int cbase = j0 + nf * 8 + (lane & 3) * 2;
#pragma unroll
                for (int jj = 0; jj < 2; jj++) {
                    int gj = cbase + jj;
                    int d0 = gi0 - gj, d1 = gi1 - gj;
                    if (d0 < 0 || d0 > WIN) s[nf][jj]     = -1e30f;
                    if (d1 < 0 || d1 > WIN) s[nf][2 + jj] = -1e30f;
                }
            }
        }

        // online softmax
        float mt0 = -1e30f, mt1 = -1e30f;
#pragma unroll
        for (int nf = 0; nf < 8; nf++) {
            mt0 = fmaxf(mt0, fmaxf(s[nf][0], s[nf][1]));
            mt1 = fmaxf(mt1, fmaxf(s[nf][2], s[nf][3]));
        }
        mt0 = fmaxf(mt0, __shfl_xor_sync(0xffffffffu, mt0, 1));
        mt0 = fmaxf(mt0, __shfl_xor_sync(0xffffffffu, mt0, 2));
        mt1 = fmaxf(mt1, __shfl_xor_sync(0xffffffffu, mt1, 1));
        mt1 = fmaxf(mt1, __shfl_xor_sync(0xffffffffu, mt1, 2));

        float mn0 = fmaxf(mi0, mt0), mn1 = fmaxf(mi1, mt1);
        float f0 = __expf(mi0 - mn0), f1 = __expf(mi1 - mn1);
        mi0 = mn0; mi1 = mn1;

        float su0 = 0.f, su1 = 0.f;
#pragma unroll
        for (int nf = 0; nf < 8; nf++) {
            s[nf][0] = __expf(s[nf][0] - mn0);
            s[nf][1] = __expf(s[nf][1] - mn0);
            s[nf][2] = __expf(s[nf][2] - mn1);
            s[nf][3] = __expf(s[nf][3] - mn1);
            su0 += s[nf][0] + s[nf][1];
            su1 += s[nf][2] + s[nf][3];
        }
        su0 += __shfl_xor_sync(0xffffffffu, su0, 1);
        su0 += __shfl_xor_sync(0xffffffffu, su0, 2);
        su1 += __shfl_xor_sync(0xffffffffu, su1, 1);
        su1 += __shfl_xor_sync(0xffffffffu, su1, 2);
        li0 = li0 * f0 + su0;
        li1 = li1 * f1 + su1;
#pragma unroll
        for (int nf = 0; nf < 8; nf++) {
            accO[nf][0] *= f0; accO[nf][1] *= f0;
            accO[nf][2] *= f1; accO[nf][3] *= f1;
        }

        // O += P V (bf16x3; P split in registers)
#pragma unroll
        for (int ks = 0; ks < 4; ks++) {
            uint32_t ph[4], pl[4];
            const float* p0 = s[2 * ks];
            const float* p1 = s[2 * ks + 1];
            ph[0] = packbf(p0[0], p0[1]);
            ph[1] = packbf(p0[2], p0[3]);
            ph[2] = packbf(p1[0], p1[1]);
            ph[3] = packbf(p1[2], p1[3]);
            pl[0] = packbf(p0[0] - __uint_as_float(ph[0] << 16),
                           p0[1] - __uint_as_float(ph[0] & 0xFFFF0000u));
            pl[1] = packbf(p0[2] - __uint_as_float(ph[1] << 16),
                           p0[3] - __uint_as_float(ph[1] & 0xFFFF0000u));
            pl[2] = packbf(p1[0] - __uint_as_float(ph[2] << 16),
                           p1[1] - __uint_as_float(ph[2] & 0xFFFF0000u));
            pl[3] = packbf(p1[2] - __uint_as_float(ph[3] << 16),
                           p1[3] - __uint_as_float(ph[3] & 0xFFFF0000u));
#pragma unroll
            for (int g2 = 0; g2 < 4; g2++) {
                uint32_t off = (uint32_t)(((ks * 16 + vr0) * APAD + g2 * 16 + vc8) * 2);
                uint32_t rh[4], rl[4];
                ldsm4t(rh, vb  + off);
                ldsm4t(rl, vbl + off);
                uint32_t bh0[2] = {rh[0], rh[1]}, bh1[2] = {rh[2], rh[3]};
                uint32_t bl0[2] = {rl[0], rl[1]}, bl1[2] = {rl[2], rl[3]};
                mma16816(accO[2*g2],   ph, bh0);
                mma16816(accO[2*g2],   ph, bl0);
                mma16816(accO[2*g2],   pl, bh0);
                mma16816(accO[2*g2+1], ph, bh1);
                mma16816(accO[2*g2+1], ph, bl1);
                mma16816(accO[2*g2+1], pl, bh1);
            }
        }
        __syncthreads();
    }

    // epilogue: scale by gate/l, split to bf16 hi/lo, store
    float g0 = gate[(bbase + gi0) * Hn + h];
    float g1 = gate[(bbase + gi1) * Hn + h];
    float sc0 = g0 / li0, sc1 = g1 / li1;
#pragma unroll
    for (int nf = 0; nf < 8; nf++) {
        int col = hoff + nf * 8 + (lane & 3) * 2;
        size_t i0 = (bbase + gi0) * (size_t)HDn + col;
        size_t i1 = (bbase + gi1) * (size_t)HDn + col;
        float o0 = accO[nf][0] * sc0, o1 = accO[nf][1] * sc0;
        uint32_t hp = packbf(o0, o1);
        uint32_t lp = packbf(o0 - __uint_as_float(hp << 16),
                             o1 - __uint_as_float(hp & 0xFFFF0000u));
        *(uint32_t*)(aoh + i0) = hp;
        *(uint32_t*)(aol + i0) = lp;
        o0 = accO[nf][2] * sc1; o1 = accO[nf][3] * sc1;
        hp = packbf(o0, o1);
        lp = packbf(o0 - __uint_as_float(hp << 16),
                    o1 - __uint_as_float(hp & 0xFFFF0000u));
        *(uint32_t*)(aoh + i1) = hp;
        *(uint32_t*)(aol + i1) = lp;
    }
}

// ---------------------------------------------------------------------------
extern "C" void kernel_launch(void* const* d_in, const int* in_sizes, int n_in,
                              void* d_out, int out_size)
{
    const float* tokens = (const float*)d_in[0];
    const float* vres   = (const float*)d_in[1];
    const float* Wq     = (const float*)d_in[2];
    const float* Wkv    = (const float*)d_in[3];
    const float* Wout   = (const float*)d_in[4];
    const float* Wgate  = (const float*)d_in[5];
    const float* Wmix   = (const float*)d_in[6];
    float* out = (float*)d_out;

    float *pq, *pk, *pv, *pmix, *pgate;
    ush *tkh, *tkl, *aoh, *aol, *wqh, *wql, *wkvh, *wkvl, *woh, *wol;
    ush *qsh, *qsl, *ksh, *ksl, *vsh, *vsl;
    cudaGetSymbolAddress((void**)&pq,   g_q);
    cudaGetSymbolAddress((void**)&pk,   g_k);
    cudaGetSymbolAddress((void**)&pv,   g_v);
    cudaGetSymbolAddress((void**)&pmix, g_mix);
    cudaGetSymbolAddress((void**)&pgate,g_gate);
    cudaGetSymbolAddress((void**)&tkh,  g_tokh);
    cudaGetSymbolAddress((void**)&tkl,  g_tokl);
    cudaGetSymbolAddress((void**)&aoh,  g_aoh);
    cudaGetSymbolAddress((void**)&aol,  g_aol);
    cudaGetSymbolAddress((void**)&wqh,  g_wqh);
    cudaGetSymbolAddress((void**)&wql,  g_wql);
    cudaGetSymbolAddress((void**)&wkvh, g_wkvh);
    cudaGetSymbolAddress((void**)&wkvl, g_wkvl);
    cudaGetSymbolAddress((void**)&woh,  g_woh);
    cudaGetSymbolAddress((void**)&wol,  g_wol);
    cudaGetSymbolAddress((void**)&qsh,  g_qsh);
    cudaGetSymbolAddress((void**)&qsl,  g_qsl);
    cudaGetSymbolAddress((void**)&ksh,  g_ksh);
    cudaGetSymbolAddress((void**)&ksl,  g_ksl);
    cudaGetSymbolAddress((void**)&vsh,  g_vsh);
    cudaGetSymbolAddress((void**)&vsl,  g_vsl);

    cudaFuncSetAttribute(gemm_mma, cudaFuncAttributeMaxDynamicSharedMemorySize, GEMM_SMEM);
    cudaFuncSetAttribute(attn_mma, cudaFuncAttributeMaxDynamicSharedMemorySize, ATT_SMEM);

    // 1. split tokens and weights into bf16 hi/lo
    convA<<<(Tn * DIMn / 4 + 255) / 256, 256>>>(tokens, tkh, tkl, Tn * DIMn / 4);
    convW<<<dim3(1024 / 32, 1024 / 32), dim3(32, 8)>>>(Wq,   wqh,  wql,  1024, 1024);
    convW<<<dim3(2048 / 32, 1024 / 32), dim3(32, 8)>>>(Wkv,  wkvh, wkvl, 1024, 2048);
    convW<<<dim3(1024 / 32, 1024 / 32), dim3(32, 8)>>>(Wout, woh,  wol,  1024, 1024);

    // 2. Q and KV projections (bf16x3 HMMA)
    gemm_mma<<<dim3(8,  64), 256, GEMM_SMEM>>>(tkh, tkl, wqh,  wql,  pq, pq);
    gemm_mma<<<dim3(16, 64), 256, GEMM_SMEM>>>(tkh, tkl, wkvh, wkvl, pk, pv);

    // 3. mix / gate logits + sigmoid
    mixgate<<<64, 256>>>(tokens, Wmix, Wgate, pmix, pgate);
    // 4. RoPE -> bf16 splits
    rope_qk<<<(Tn * Hn * 32) / 256, 256>>>(pq, pk, qsh, qsl, ksh, ksl);
    // 5. v lerp with residual -> bf16 splits
    vmix<<<(Tn * HDn / 2) / 256, 256>>>(pv, vres, pmix, vsh, vsl);
    // 6. windowed attention on tensor cores (+gate), writes ao splits
    attn_mma<<<dim3(Sn / 64, Hn, Bn), 128, ATT_SMEM>>>(
        qsh, qsl, ksh, ksl, vsh, vsl, pgate, aoh, aol);
    // 7. output projection into d_out
    gemm_mma<<<dim3(8, 64), 256, GEMM_SMEM>>>(aoh, aol, woh, wol, out, out);
}

// round 5
// speedup vs baseline: 2.4894x; 1.0581x over previous
#include <cuda_runtime.h>
#include <cuda_bf16.h>
#include <math.h>
#include <stdint.h>

// Problem constants
#define Bn 4
#define Sn 2048
#define DIMn 1024
#define Hn 16
#define Dn 64
#define Tn (Bn*Sn)      // 8192 tokens
#define HDn 1024
#define WIN 512

typedef unsigned short ush;

// ---------------------------------------------------------------------------
// Scratch (device globals)
// ---------------------------------------------------------------------------
__device__ float g_mix[Tn*Hn];
__device__ float g_gate[Tn*Hn];

__device__ ush g_tokh[(size_t)Tn*DIMn];
__device__ ush g_tokl[(size_t)Tn*DIMn];
__device__ ush g_aoh[(size_t)Tn*HDn];
__device__ ush g_aol[(size_t)Tn*HDn];
__device__ ush g_wallh[3072*1024];   // [Wq | Wk | Wv] transposed, [N=3072, K=1024]
__device__ ush g_walll[3072*1024];
__device__ ush g_woh[1024*1024];
__device__ ush g_wol[1024*1024];
// post-rope / post-vmix bf16 splits
__device__ ush g_qsh[(size_t)Tn*HDn];
__device__ ush g_qsl[(size_t)Tn*HDn];
__device__ ush g_ksh[(size_t)Tn*HDn];
__device__ ush g_ksl[(size_t)Tn*HDn];
__device__ ush g_vsh[(size_t)Tn*HDn];
__device__ ush g_vsl[(size_t)Tn*HDn];

// ---------------------------------------------------------------------------
// Helpers (base sm_103 target — mma.sync / ldmatrix / cp.async, NO tcgen05)
// ---------------------------------------------------------------------------
__device__ __forceinline__ uint32_t smem_u32(const void* p) {
    uint32_t a;
    asm("{ .reg .u64 t; cvta.to.shared.u64 t, %1; cvt.u32.u64 %0, t; }" : "=r"(a) : "l"(p));
    return a;
}
__device__ __forceinline__ void ldsm4(uint32_t* r, uint32_t addr) {
    asm volatile("ldmatrix.sync.aligned.m8n8.x4.shared.b16 {%0,%1,%2,%3}, [%4];"
                 : "=r"(r[0]), "=r"(r[1]), "=r"(r[2]), "=r"(r[3]) : "r"(addr));
}
__device__ __forceinline__ void ldsm4t(uint32_t* r, uint32_t addr) {
    asm volatile("ldmatrix.sync.aligned.m8n8.x4.trans.shared.b16 {%0,%1,%2,%3}, [%4];"
                 : "=r"(r[0]), "=r"(r[1]), "=r"(r[2]), "=r"(r[3]) : "r"(addr));
}
__device__ __forceinline__ void mma16816(float* d, const uint32_t* a, const uint32_t* b) {
    asm volatile("mma.sync.aligned.m16n8k16.row.col.f32.bf16.bf16.f32 "
                 "{%0,%1,%2,%3},{%4,%5,%6,%7},{%8,%9},{%0,%1,%2,%3};"
                 : "+f"(d[0]), "+f"(d[1]), "+f"(d[2]), "+f"(d[3])
                 : "r"(a[0]), "r"(a[1]), "r"(a[2]), "r"(a[3]),
                   "r"(b[0]), "r"(b[1]));
}
__device__ __forceinline__ void cp16(uint32_t smem, const void* g) {
    asm volatile("cp.async.cg.shared.global [%0], [%1], 16;" :: "r"(smem), "l"(g));
}
// pack two fp32 -> bf16x2 (first arg -> low 16 bits)
__device__ __forceinline__ uint32_t packbf(float lo, float hi) {
    uint32_t r;
    asm("cvt.rn.bf16x2.f32 %0, %1, %2;" : "=r"(r) : "f"(hi), "f"(lo));
    return r;
}
__device__ __forceinline__ void split2(float x, ush& h, ush& l) {
    __nv_bfloat16 hb = __float2bfloat16_rn(x);
    float r = x - __bfloat162float(hb);
    __nv_bfloat16 lb = __float2bfloat16_rn(r);
    h = *reinterpret_cast<ush*>(&hb);
    l = *reinterpret_cast<ush*>(&lb);
}
// split a pair -> packed hi word / lo word
__device__ __forceinline__ void splitpair(float y0, float y1, uint32_t& hp, uint32_t& lp) {
    hp = packbf(y0, y1);
    lp = packbf(y0 - __uint_as_float(hp << 16),
                y1 - __uint_as_float(hp & 0xFFFF0000u));
}

// ---------------------------------------------------------------------------
// fp32 -> bf16 hi/lo split (elementwise)
// ---------------------------------------------------------------------------
__global__ void convA(const float* __restrict__ x, ush* __restrict__ h,
                      ush* __restrict__ l, int n4)
{
    int i = blockIdx.x * blockDim.x + threadIdx.x;
    if (i >= n4) return;
    float4 v = ((const float4*)x)[i];
    float vs[4] = {v.x, v.y, v.z, v.w};
    ush hs[4], ls[4];
#pragma unroll
    for (int j = 0; j < 4; j++) split2(vs[j], hs[j], ls[j]);
    ((ushort4*)h)[i] = make_ushort4(hs[0], hs[1], hs[2], hs[3]);
    ((ushort4*)l)[i] = make_ushort4(ls[0], ls[1], ls[2], ls[3]);
}

// W [K,N] fp32 -> Wt_hi/lo [N,K] bf16 (transpose via smem); dst may be offset.
__global__ void convW(const float* __restrict__ W, ush* __restrict__ Th,
                      ush* __restrict__ Tl, int K, int N)
{
    __shared__ float t[32][33];
    int n0 = blockIdx.x * 32, k0 = blockIdx.y * 32;
    int tx = threadIdx.x, ty = threadIdx.y;   // blockDim (32, 8)
#pragma unroll
    for (int r = 0; r < 4; r++)
        t[ty + 8 * r][tx] = W[(size_t)(k0 + ty + 8 * r) * N + n0 + tx];
    __syncthreads();
#pragma unroll
    for (int r = 0; r < 4; r++) {
        float v = t[tx][ty + 8 * r];
        size_t o = (size_t)(n0 + ty + 8 * r) * K + k0 + tx;
        ush hh, ll;
        split2(v, hh, ll);
        Th[o] = hh; Tl[o] = ll;
    }
}

// ---------------------------------------------------------------------------
// HMMA bf16x3 GEMM, cp.async pipelined. CTA 128x128, 8 warps, K-chunk 32.
// mode 0: C fp32 (Wout projection)
// mode 1: fused QKV epilogue: seg0 rope+scale->q splits, seg1 rope->k splits,
//         seg2 v-mix->v splits.
// ---------------------------------------------------------------------------
#define PADE 40
#define TILE_ELEMS (128*PADE)
#define GEMM_SMEM (2*4*TILE_ELEMS*2)

__global__ void __launch_bounds__(256) gemm_mma(
    const ush* __restrict__ Ah, const ush* __restrict__ Al,
    const ush* __restrict__ Bh, const ush* __restrict__ Bl,
    float* __restrict__ C,
    ush* __restrict__ qh, ush* __restrict__ ql,
    ush* __restrict__ kh, ush* __restrict__ kl,
    ush* __restrict__ vh, ush* __restrict__ vl,
    const float* __restrict__ vres, const float* __restrict__ mix,
    int mode)
{
    extern __shared__ ush sh[];
    const int tid  = threadIdx.x;
    const int wid  = tid >> 5, lane = tid & 31;
    const int brow = blockIdx.y * 128, bcol = blockIdx.x * 128;
    const int wm   = (wid & 3) * 32;
    const int wn   = (wid >> 2) * 64;
    const int K    = 1024;

    const uint32_t sbase = smem_u32(sh);

    float acc[2][8][4];
#pragma unroll
    for (int i = 0; i < 2; i++)
#pragma unroll
        for (int j = 0; j < 8; j++)
#pragma unroll
            for (int k = 0; k < 4; k++) acc[i][j][k] = 0.f;

    const ush* srcs[4] = {Ah, Al, Bh, Bl};
    const int rbase[4] = {brow, brow, bcol, bcol};

    auto cp_chunk = [&](int k0, int buf) {
#pragma unroll
        for (int kind = 0; kind < 4; kind++) {
#pragma unroll
            for (int half = 0; half < 2; half++) {
                int e = tid + half * 256;          // 0..511
                int row = e >> 2, ce = (e & 3) * 8;
                const ush* g = srcs[kind] + (size_t)(rbase[kind] + row) * K + k0 + ce;
                uint32_t d = sbase + (uint32_t)(buf * 4 * TILE_ELEMS +
                             kind * TILE_ELEMS + row * PADE + ce) * 2;
                cp16(d, g);
            }
        }
        asm volatile("cp.async.commit_group;" ::: "memory");
    };

    cp_chunk(0, 0);

    for (int c = 0; c < 32; c++) {
        int buf = c & 1;
        if (c < 31) {
            cp_chunk((c + 1) * 32, buf ^ 1);
            asm volatile("cp.async.wait_group 1;" ::: "memory");
        } else {
            asm volatile("cp.async.wait_group 0;" ::: "memory");
        }
        __syncthreads();

        uint32_t abase = sbase + buf * 4 * TILE_ELEMS * 2;

#pragma unroll
        for (int ksub = 0; ksub < 2; ksub++) {
            uint32_t a[2][2][4];
            {
                int arow = wm + (lane & 15);
                int acol = ksub * 16 + (lane >> 4) * 8;
#pragma unroll
                for (int sp = 0; sp < 2; sp++)
#pragma unroll
                    for (int ms = 0; ms < 2; ms++)
                        ldsm4(a[sp][ms], abase + sp * TILE_ELEMS * 2 +
                              ((arow + ms * 16) * PADE + acol) * 2);
            }
            uint32_t b[2][8][2];
            {
                int bn = (lane & 7) | ((lane >> 1) & 8);
                int bk = ksub * 16 + ((lane >> 3) & 1) * 8;
#pragma unroll
                for (int sp = 0; sp < 2; sp++)
#pragma unroll
                    for (int g = 0; g < 4; g++) {
                        uint32_t r[4];
                        ldsm4(r, abase + (2 + sp) * TILE_ELEMS * 2 +
                              ((wn + g * 16 + bn) * PADE + bk) * 2);
                        b[sp][2 * g][0]     = r[0]; b[sp][2 * g][1]     = r[1];
                        b[sp][2 * g + 1][0] = r[2]; b[sp][2 * g + 1][1] = r[3];
                    }
            }
#pragma unroll
            for (int ms = 0; ms < 2; ms++)
#pragma unroll
                for (int nf = 0; nf < 8; nf++) {
                    mma16816(acc[ms][nf], a[0][ms], b[0][nf]);
                    mma16816(acc[ms][nf], a[0][ms], b[1][nf]);
                    mma16816(acc[ms][nf], a[1][ms], b[0][nf]);
                }
        }
        __syncthreads();
    }

    if (mode == 0) {
        // plain fp32 store
#pragma unroll
        for (int ms = 0; ms < 2; ms++) {
            int r0 = brow + wm + ms * 16 + (lane >> 2);
#pragma unroll
            for (int nf = 0; nf < 8; nf++) {
                int cc = bcol + wn + nf * 8 + 2 * (lane & 3);
                *(float2*)(C + (size_t)r0 * 1024 + cc)       = make_float2(acc[ms][nf][0], acc[ms][nf][1]);
                *(float2*)(C + (size_t)(r0 + 8) * 1024 + cc) = make_float2(acc[ms][nf][2], acc[ms][nf][3]);
            }
        }
        return;
    }

    // fused QKV epilogue
    const int seg  = bcol >> 10;          // 0=q, 1=k, 2=v
    const int colb = (bcol & 1023) + wn + 2 * (lane & 3);
    ush* dh = (seg == 0) ? qh : (seg == 1) ? kh : vh;
    ush* dl = (seg == 0) ? ql : (seg == 1) ? kl : vl;
    const float qscale = (seg == 0) ? 0.125f : 1.0f;

#pragma unroll
    for (int ms = 0; ms < 2; ms++) {
        int r0 = brow + wm + ms * 16 + (lane >> 2);
#pragma unroll
        for (int half = 0; half < 2; half++) {
            int row = r0 + half * 8;
            int s = row & (Sn - 1);
            int bb = row >> 11;
#pragma unroll
            for (int nf = 0; nf < 8; nf++) {
                float x0 = acc[ms][nf][half * 2 + 0];
                float x1 = acc[ms][nf][half * 2 + 1];
                int colc = colb + nf * 8;
                float y0, y1;
                if (seg < 2) {
                    int i = (colc & 63) >> 1;
                    float inv = powf(10000.0f, -(float)(2 * i) * (1.0f / 64.0f));
                    float ang = (float)s * inv;
                    float sn, cs;
                    sincosf(ang, &sn, &cs);
                    y0 = (x0 * cs - x1 * sn) * qscale;
                    y1 = (x1 * cs + x0 * sn) * qscale;
                } else {
                    int hh = (colc & 1023) >> 6;
                    int d  = colc & 63;
                    float m = mix[row * Hn + hh];
                    const float* rp = vres + (((size_t)bb * Hn + hh) * Sn + s) * Dn + d;
                    float2 rr = *(const float2*)rp;
                    y0 = x0 + (rr.x - x0) * m;
                    y1 = x1 + (rr.y - x1) * m;
                }
                uint32_t hp, lp;
                splitpair(y0, y1, hp, lp);
                size_t o = (size_t)row * 1024 + colc;
                *(uint32_t*)(dh + o) = hp;
                *(uint32_t*)(dl + o) = lp;
            }
        }
    }
}

// ---------------------------------------------------------------------------
// mix/gate: (8192 x 1024) @ [Wmix | Wgate] (1024 x 32), sigmoid epilogue.
// ---------------------------------------------------------------------------
__global__ void __launch_bounds__(256) mixgate(
    const float* __restrict__ tokens, const float* __restrict__ Wmix,
    const float* __restrict__ Wgate, float* __restrict__ gmix,
    float* __restrict__ ggate)
{
    __shared__ float Ts[128][65];
    __shared__ float Ws[64][32];

    const int tid  = threadIdx.x;
    const int row0 = blockIdx.x * 128;
    const int r  = tid >> 1;
    const int cg = (tid & 1) << 4;

    float acc[16];
#pragma unroll
    for (int c = 0; c < 16; c++) acc[c] = 0.f;

    for (int k0 = 0; k0 < 1024; k0 += 64) {
#pragma unroll
        for (int u = 0; u < 8; u++) {
            int fi = tid + u * 256;
            int rr = fi >> 4;
            int cc = (fi & 15) << 2;
            float4 x = *(const float4*)(tokens + (size_t)(row0 + rr) * 1024 + k0 + cc);
            Ts[rr][cc] = x.x; Ts[rr][cc + 1] = x.y; Ts[rr][cc + 2] = x.z; Ts[rr][cc + 3] = x.w;
        }
#pragma unroll
        for (int u = 0; u < 8; u++) {
            int fi = tid + u * 256;
            int rr = fi >> 5;
            int cc = fi & 31;
            Ws[rr][cc] = (cc < 16) ? Wmix[(k0 + rr) * 16 + cc]
                                   : Wgate[(k0 + rr) * 16 + (cc - 16)];
        }
        __syncthreads();
        for (int kk = 0; kk < 64; kk++) {
            float a = Ts[r][kk];
#pragma unroll
            for (int c = 0; c < 16; c++) acc[c] += a * Ws[kk][cg + c];
        }
        __syncthreads();
    }

    const int t = row0 + r;
#pragma unroll
    for (int c = 0; c < 16; c++) {
        float sg = 1.0f / (1.0f + expf(-acc[c]));
        int col = cg + c;
        if (col < 16) gmix[t * 16 + col] = sg;
        else          ggate[t * 16 + (col - 16)] = sg;
    }
}

// ---------------------------------------------------------------------------
// Sliding-window flash attention, HMMA bf16x3, online softmax in registers.
// CTA = (64-query tile, head, batch); 4 warps, warp = 16 rows x 64 keys.
// ---------------------------------------------------------------------------
#define APAD 72
#define ATT_SMEM (6*64*APAD*2)

__global__ void __launch_bounds__(128) attn_mma(
    const ush* __restrict__ qh, const ush* __restrict__ ql,
    const ush* __restrict__ kh, const ush* __restrict__ kl,
    const ush* __restrict__ vh, const ush* __restrict__ vl,
    const float* __restrict__ gate,
    ush* __restrict__ aoh, ush* __restrict__ aol)
{
    extern __shared__ ush smA[];
    ush* Qh = smA;
    ush* Ql = Qh + 64 * APAD;
    ush* Kh = Ql + 64 * APAD;
    ush* Kl = Kh + 64 * APAD;
    ush* Vh = Kl + 64 * APAD;
    ush* Vl = Vh + 64 * APAD;

    const int b = blockIdx.z, h = blockIdx.y, q0 = blockIdx.x * 64;
    const int tid = threadIdx.x, wid = tid >> 5, lane = tid & 31;
    const int wm = wid * 16;
    const size_t bbase = (size_t)b * Sn;
    const int hoff = h * Dn;

#pragma unroll
    for (int i = 0; i < 4; i++) {
        int e = tid + i * 128;
        int row = e >> 3, c = (e & 7) * 8;
        size_t g = (bbase + q0 + row) * (size_t)HDn + hoff + c;
        *(uint4*)(Qh + row * APAD + c) = *(const uint4*)(qh + g);
        *(uint4*)(Ql + row * APAD + c) = *(const uint4*)(ql + g);
    }
    __syncthreads();

    uint32_t qfh[4][4], qfl[4][4];
    {
        uint32_t qb = smem_u32(Qh), qbl = smem_u32(Ql);
        int arow = wm + (lane & 15);
        int ac0  = (lane >> 4) * 8;
#pragma unroll
        for (int ks = 0; ks < 4; ks++) {
            ldsm4(qfh[ks], qb  + (arow * APAD + ks * 16 + ac0) * 2);
            ldsm4(qfl[ks], qbl + (arow * APAD + ks * 16 + ac0) * 2);
        }
    }

    float mi0 = -1e30f, mi1 = -1e30f, li0 = 0.f, li1 = 0.f;
    float accO[8][4];
#pragma unroll
    for (int i = 0; i < 8; i++)
#pragma unroll
        for (int j = 0; j < 4; j++) accO[i][j] = 0.f;

    const int jt_lo = (q0 >= WIN) ? ((q0 - WIN) >> 6) : 0;
    const int jt_hi = q0 >> 6;
    const int gi0 = q0 + wm + (lane >> 2);
    const int gi1 = gi0 + 8;

    const uint32_t kb  = smem_u32(Kh), kbl = smem_u32(Kl);
    const uint32_t vb  = smem_u32(Vh), vbl = smem_u32(Vl);
    const int bn  = (lane & 7) | ((lane >> 1) & 8);
    const int bk8 = ((lane >> 3) & 1) * 8;
    const int vr0 = lane & 15;
    const int vc8 = (lane >> 4) * 8;

    for (int jt = jt_lo; jt <= jt_hi; jt++) {
        const int j0 = jt * 64;
#pragma unroll
        for (int i = 0; i < 4; i++) {
            int e = tid + i * 128;
            int row = e >> 3, c = (e & 7) * 8;
            size_t g = (bbase + j0 + row) * (size_t)HDn + hoff + c;
            *(uint4*)(Kh + row * APAD + c) = *(const uint4*)(kh + g);
            *(uint4*)(Kl + row * APAD + c) = *(const uint4*)(kl + g);
            *(uint4*)(Vh + row * APAD + c) = *(const uint4*)(vh + g);
            *(uint4*)(Vl + row * APAD + c) = *(const uint4*)(vl + g);
        }
        __syncthreads();

        float s[8][4];
#pragma unroll
        for (int i = 0; i < 8; i++)
#pragma unroll
            for (int j = 0; j < 4; j++) s[i][j] = 0.f;

#pragma unroll
        for (int ks = 0; ks < 4; ks++) {
#pragma unroll
            for (int g2 = 0; g2 < 4; g2++) {
                uint32_t off = (uint32_t)(((g2 * 16 + bn) * APAD + ks * 16 + bk8) * 2);
                uint32_t rh[4], rl[4];
                ldsm4(rh, kb  + off);
                ldsm4(rl, kbl + off);
                uint32_t bh0[2] = {rh[0], rh[1]}, bh1[2] = {rh[2], rh[3]};
                uint32_t bl0[2] = {rl[0], rl[1]}, bl1[2] = {rl[2], rl[3]};
                mma16816(s[2*g2],   qfh[ks], bh0);
                mma16816(s[2*g2],   qfh[ks], bl0);
                mma16816(s[2*g2],   qfl[ks], bh0);
                mma16816(s[2*g2+1], qfh[ks], bh1);
                mma16816(s[2*g2+1], qfh[ks], bl1);
                mma16816(s[2*g2+1], qfl[ks], bh1);
            }
        }

        if (jt == jt_hi || (jt == jt_lo && q0 >= WIN)) {
#pragma unroll
            for (int nf = 0; nf < 8; nf++) {
                int cbase = j0 + nf * 8 + (lane & 3) * 2;
#pragma unroll
                for (int jj = 0; jj < 2; jj++) {
                    int gj = cbase + jj;
                    int d0 = gi0 - gj, d1 = gi1 - gj;
                    if (d0 < 0 || d0 > WIN) s[nf][jj]     = -1e30f;
                    if (d1 < 0 || d1 > WIN) s[nf][2 + jj] = -1e30f;
                }
            }
        }

        float mt0 = -1e30f, mt1 = -1e30f;
#pragma unroll
        for (int nf = 0; nf < 8; nf++) {
            mt0 = fmaxf(mt0, fmaxf(s[nf][0], s[nf][1]));
            mt1 = fmaxf(mt1, fmaxf(s[nf][2], s[nf][3]));
        }
        mt0 = fmaxf(mt0, __shfl_xor_sync(0xffffffffu, mt0, 1));
        mt0 = fmaxf(mt0, __shfl_xor_sync(0xffffffffu, mt0, 2));
        mt1 = fmaxf(mt1, __shfl_xor_sync(0xffffffffu, mt1, 1));
        mt1 = fmaxf(mt1, __shfl_xor_sync(0xffffffffu, mt1, 2));

        float mn0 = fmaxf(mi0, mt0), mn1 = fmaxf(mi1, mt1);
        float f0 = __expf(mi0 - mn0), f1 = __expf(mi1 - mn1);
        mi0 = mn0; mi1 = mn1;

        float su0 = 0.f, su1 = 0.f;
#pragma unroll
        for (int nf = 0; nf < 8; nf++) {
            s[nf][0] = __expf(s[nf][0] - mn0);
            s[nf][1] = __expf(s[nf][1] - mn0);
            s[nf][2] = __expf(s[nf][2] - mn1);
            s[nf][3] = __expf(s[nf][3] - mn1);
            su0 += s[nf][0] + s[nf][1];
            su1 += s[nf][2] + s[nf][3];
        }
        su0 += __shfl_xor_sync(0xffffffffu, su0, 1);
        su0 += __shfl_xor_sync(0xffffffffu, su0, 2);
        su1 += __shfl_xor_sync(0xffffffffu, su1, 1);
        su1 += __shfl_xor_sync(0xffffffffu, su1, 2);
        li0 = li0 * f0 + su0;
        li1 = li1 * f1 + su1;
#pragma unroll
        for (int nf = 0; nf < 8; nf++) {
            accO[nf][0] *= f0; accO[nf][1] *= f0;
            accO[nf][2] *= f1; accO[nf][3] *= f1;
        }

#pragma unroll
        for (int ks = 0; ks < 4; ks++) {
            uint32_t ph[4], pl[4];
            const float* p0 = s[2 * ks];
            const float* p1 = s[2 * ks + 1];
            splitpair(p0[0], p0[1], ph[0], pl[0]);
            splitpair(p0[2], p0[3], ph[1], pl[1]);
            splitpair(p1[0], p1[1], ph[2], pl[2]);
            splitpair(p1[2], p1[3], ph[3], pl[3]);
#pragma unroll
            for (int g2 = 0; g2 < 4; g2++) {
                uint32_t off = (uint32_t)(((ks * 16 + vr0) * APAD + g2 * 16 + vc8) * 2);
                uint32_t rh[4], rl[4];
                ldsm4t(rh, vb  + off);
                ldsm4t(rl, vbl + off);
                uint32_t bh0[2] = {rh[0], rh[1]}, bh1[2] = {rh[2], rh[3]};
                uint32_t bl0[2] = {rl[0], rl[1]}, bl1[2] = {rl[2], rl[3]};
                mma16816(accO[2*g2],   ph, bh0);
                mma16816(accO[2*g2],   ph, bl0);
                mma16816(accO[2*g2],   pl, bh0);
                mma16816(accO[2*g2+1], ph, bh1);
                mma16816(accO[2*g2+1], ph, bl1);
                mma16816(accO[2*g2+1], pl, bh1);
            }
        }
        __syncthreads();
    }

    float g0 = gate[(bbase + gi0) * Hn + h];
    float g1 = gate[(bbase + gi1) * Hn + h];
    float sc0 = g0 / li0, sc1 = g1 / li1;
#pragma unroll
    for (int nf = 0; nf < 8; nf++) {
        int col = hoff + nf * 8 + (lane & 3) * 2;
        size_t i0 = (bbase + gi0) * (size_t)HDn + col;
        size_t i1 = (bbase + gi1) * (size_t)HDn + col;
        uint32_t hp, lp;
        splitpair(accO[nf][0] * sc0, accO[nf][1] * sc0, hp, lp);
        *(uint32_t*)(aoh + i0) = hp;
        *(uint32_t*)(aol + i0) = lp;
        splitpair(accO[nf][2] * sc1, accO[nf][3] * sc1, hp, lp);
        *(uint32_t*)(aoh + i1) = hp;
        *(uint32_t*)(aol + i1) = lp;
    }
}

// ---------------------------------------------------------------------------
extern "C" void kernel_launch(void* const* d_in, const int* in_sizes, int n_in,
                              void* d_out, int out_size)
{
    const float* tokens = (const float*)d_in[0];
    const float* vres   = (const float*)d_in[1];
    const float* Wq     = (const float*)d_in[2];
    const float* Wkv    = (const float*)d_in[3];
    const float* Wout   = (const float*)d_in[4];
    const float* Wgate  = (const float*)d_in[5];
    const float* Wmix   = (const float*)d_in[6];
    float* out = (float*)d_out;

    float *pmix, *pgate;
    ush *tkh, *tkl, *aoh, *aol, *wah, *wal, *woh, *wol;
    ush *qsh, *qsl, *ksh, *ksl, *vsh, *vsl;
    cudaGetSymbolAddress((void**)&pmix, g_mix);
    cudaGetSymbolAddress((void**)&pgate,g_gate);
    cudaGetSymbolAddress((void**)&tkh,  g_tokh);
    cudaGetSymbolAddress((void**)&tkl,  g_tokl);
    cudaGetSymbolAddress((void**)&aoh,  g_aoh);
    cudaGetSymbolAddress((void**)&aol,  g_aol);
    cudaGetSymbolAddress((void**)&wah,  g_wallh);
    cudaGetSymbolAddress((void**)&wal,  g_walll);
    cudaGetSymbolAddress((void**)&woh,  g_woh);
    cudaGetSymbolAddress((void**)&wol,  g_wol);
    cudaGetSymbolAddress((void**)&qsh,  g_qsh);
    cudaGetSymbolAddress((void**)&qsl,  g_qsl);
    cudaGetSymbolAddress((void**)&ksh,  g_ksh);
    cudaGetSymbolAddress((void**)&ksl,  g_ksl);
    cudaGetSymbolAddress((void**)&vsh,  g_vsh);
    cudaGetSymbolAddress((void**)&vsl,  g_vsl);

    cudaFuncSetAttribute(gemm_mma, cudaFuncAttributeMaxDynamicSharedMemorySize, GEMM_SMEM);
    cudaFuncSetAttribute(attn_mma, cudaFuncAttributeMaxDynamicSharedMemorySize, ATT_SMEM);

    // 1. splits: tokens; merged weight wall = [Wq rows | Wkv rows]; Wout
    convA<<<(Tn * DIMn / 4 + 255) / 256, 256>>>(tokens, tkh, tkl, Tn * DIMn / 4);
    convW<<<dim3(1024 / 32, 1024 / 32), dim3(32, 8)>>>(Wq,  wah,               wal,               1024, 1024);
    convW<<<dim3(2048 / 32, 1024 / 32), dim3(32, 8)>>>(Wkv, wah + 1024 * 1024, wal + 1024 * 1024, 1024, 2048);
    convW<<<dim3(1024 / 32, 1024 / 32), dim3(32, 8)>>>(Wout, woh, wol, 1024, 1024);

    // 2. mix / gate logits + sigmoid (mix needed by fused QKV epilogue)
    mixgate<<<64, 256>>>(tokens, Wmix, Wgate, pmix, pgate);

    // 3. merged QKV projection with fused rope / v-mix epilogue
    gemm_mma<<<dim3(24, 64), 256, GEMM_SMEM>>>(
        tkh, tkl, wah, wal, nullptr,
        qsh, qsl, ksh, ksl, vsh, vsl, vres, pmix, 1);

    // 4. windowed attention on tensor cores (+gate), writes ao splits
    attn_mma<<<dim3(Sn / 64, Hn, Bn), 128, ATT_SMEM>>>(
        qsh, qsl, ksh, ksl, vsh, vsl, pgate, aoh, aol);

    // 5. output projection into d_out
    gemm_mma<<<dim3(8, 64), 256, GEMM_SMEM>>>(
        aoh, aol, woh, wol, out,
        nullptr, nullptr, nullptr, nullptr, nullptr, nullptr, nullptr, nullptr, 0);
}